// round 15
// baseline (speedup 1.0000x reference)
#include <cuda_runtime.h>
#include <cuda_fp16.h>
#include <math.h>

#define B_ 8
#define T_ 512
#define C_ 512
#define H_ 8
#define F_ 2048
#define WIN_ 10

#define ELT_X (B_*C_*T_)
#define ELT_P (B_*H_*T_*T_)
#define WQKV ((size_t)6*C_*C_)
#define WFF  ((size_t)6*F_*C_*3)

#define HALFS ((size_t)5*ELT_X + (size_t)B_*516*(C_+F_) + 4*WQKV + 2*WFF + ELT_P)
__device__ float g_pool[(size_t)5*ELT_X + ELT_P + (HALFS+1)/2];

__device__ __forceinline__ void mma_f16(float c[4], const unsigned a[4], const unsigned b[2]){
    asm("mma.sync.aligned.m16n8k16.row.col.f32.f16.f16.f32 "
        "{%0,%1,%2,%3}, {%4,%5,%6,%7}, {%8,%9}, {%0,%1,%2,%3};"
        : "+f"(c[0]), "+f"(c[1]), "+f"(c[2]), "+f"(c[3])
        : "r"(a[0]), "r"(a[1]), "r"(a[2]), "r"(a[3]), "r"(b[0]), "r"(b[1]));
}
__device__ __forceinline__ void cp16(void* smem, const void* g){
    unsigned s = (unsigned)__cvta_generic_to_shared(smem);
    asm volatile("cp.async.ca.shared.global [%0], [%1], 16;" :: "r"(s), "l"(g));
}
#define CP_COMMIT asm volatile("cp.async.commit_group;" ::: "memory")
#define CP_WAIT2  asm volatile("cp.async.wait_group 2;" ::: "memory")

/* ===== fp16 dense weight swizzle ===== */
__global__ void k_swizA16(const float* __restrict__ S, __half* __restrict__ D,
                          int Ktot, size_t msz, size_t total)
{
    size_t idx = (size_t)blockIdx.x*256 + threadIdx.x;
    if (idx >= total) return;
    size_t l = idx / msz;
    size_t od = idx - l*msz;
    int mtile = (int)(od / ((size_t)Ktot*128));
    int rem = (int)(od - (size_t)mtile*Ktot*128);
    int ktile = rem >> 12;
    int rem2 = rem & 4095;
    int mgrp = rem2 >> 9;
    int rem3 = rem2 & 511;
    int ks = rem3 >> 8;
    int rem4 = rem3 & 255;
    int lane = rem4 >> 3;
    int u = rem4 & 7;
    int reg = u >> 1, hh = u & 1;
    int gid = lane >> 2, tig = lane & 3;
    int m = mtile*128 + mgrp*16 + gid + (reg&1)*8;
    int k = ktile*32 + ks*16 + tig*2 + hh + (reg>>1)*8;
    D[idx] = __float2half_rn(S[l*msz + (size_t)m*Ktot + k]);
}

/* ===== fp16 conv weight swizzle ===== */
__global__ void k_swizC16(const float* __restrict__ S, __half* __restrict__ D,
                          int Cin, size_t msz3, size_t total)
{
    size_t idx = (size_t)blockIdx.x*256 + threadIdx.x;
    if (idx >= total) return;
    size_t l = idx / msz3;
    size_t od = idx - l*msz3;
    int mtile = (int)(od / ((size_t)Cin*384));
    int rem = (int)(od - (size_t)mtile*Cin*384);
    int ctile = rem / 6144;
    int rem2 = rem % 6144;
    int tap = rem2 >> 11;
    int rem3 = rem2 & 2047;
    int mgrp = rem3 >> 8;
    int rem4 = rem3 & 255;
    int lane = rem4 >> 3;
    int u = rem4 & 7;
    int reg = u >> 1, hh = u & 1;
    int gid = lane >> 2, tig = lane & 3;
    int m = mtile*128 + mgrp*16 + gid + (reg&1)*8;
    int c = ctile*16 + tig*2 + hh + (reg>>1)*8;
    D[idx] = __float2half_rn(S[l*msz3 + (size_t)m*Cin*3 + (size_t)c*3 + tap]);
}

/* ---- mask: px fp32 + hXr packed-pair fp16 ---- */
__global__ void k_maskmul2(const float* __restrict__ X, const float* __restrict__ mask,
                           float* __restrict__ Y, __half* __restrict__ Xr)
{
    int i = blockIdx.x*256 + threadIdx.x;
    int t = i & (T_-1);
    int c = (i >> 9) & (C_-1);
    int b = i >> 18;
    float v = X[i] * mask[b*T_ + t];
    Y[i] = v;
    Xr[((size_t)(b*256 + (c>>1))*T_ + t)*2 + (c&1)] = __float2half_rn(v);
}
__global__ void k_maskmul(const float* __restrict__ X, const float* __restrict__ mask,
                          float* __restrict__ Y)
{
    int i = blockIdx.x*256 + threadIdx.x;
    int t = i & (T_-1);
    int b = i / (C_*T_);
    Y[i] = X[i] * mask[b*T_ + t];
}

/* ---- zero border rows of hXp1 / hXp2 ---- */
__global__ void k_zb16(__half* __restrict__ Xp1, __half* __restrict__ Xp2)
{
    int idx2 = blockIdx.x*256 + threadIdx.x;
    if (idx2 < 4096){
        int b = idx2 >> 9, rr = (idx2 >> 8) & 1, off = idx2 & 255;
        ((__half2*)Xp1)[((size_t)(b*516 + rr*513)*C_)/2 + off] = __half2half2(__float2half(0.f));
    } else {
        int j = idx2 - 4096;
        int b = j >> 11, rr = (j >> 10) & 1, off = j & 1023;
        ((__half2*)Xp2)[((size_t)(b*516 + rr*513)*F_)/2 + off] = __half2half2(__float2half(0.f));
    }
}

#define LOAD_AF16(af, sAh, wm, ks1, lane) \
    _Pragma("unroll") \
    for (int i=0;i<4;i++){ \
        const float4 av = *(const float4*)((sAh) + ((((wm)*4+i)*2+(ks1))*32 + (lane))*8); \
        af[i][0]=__float_as_uint(av.x); af[i][1]=__float_as_uint(av.y); \
        af[i][2]=__float_as_uint(av.z); af[i][3]=__float_as_uint(av.w); \
    }

/* =========== fp16 1x1 GEMM (Wo), split-K x2, raw fp32 partials ============ */
__launch_bounds__(256,2)
__global__ void g1x1(const __half* __restrict__ Wm, const __half* __restrict__ X2h,
                     float* __restrict__ Y)
{
    extern __shared__ char smraw[];
    __half* sA = (__half*)smraw;
    __half2* sB2 = (__half2*)(smraw + 4*4096*2);
    unsigned* sBu = (unsigned*)sB2;
    const int n0 = blockIdx.x*128;
    const int m0 = blockIdx.y*128;
    const int bz = blockIdx.z;
    const int b  = bz & 7;
    const int part = bz >> 3;
    const int kOff = part*256;
    const int tid = threadIdx.x;
    const int lane = tid & 31, wid = tid >> 5;
    const int gid = lane >> 2, tig = lane & 3;
    const int wm = wid & 1, wn = wid >> 1;

    const __half2* X2 = (const __half2*)X2h + (size_t)b*256*T_;
    const int rowB = tid >> 4, colB = (tid & 15)*8;

    float acc[4][4][4];
#pragma unroll
    for (int i=0;i<4;i++)
#pragma unroll
        for (int j=0;j<4;j++)
#pragma unroll
            for (int u=0;u<4;u++) acc[i][j][u]=0.f;

    const int KT = 8;   /* 256/32 */
#define ST_A(st,K0) { const __half* ap = Wm + (size_t)(m0>>7)*65536 + (size_t)((K0)>>5)*4096 + tid*16; \
                      __half* d = sA + (st)*4096 + tid*16; cp16(d,ap); cp16(d+8,ap+8); }
#define ST_B(st,K0) { const __half2* bp = X2 + (size_t)(((K0)>>1) + rowB)*T_ + n0 + colB; \
                      __half2* d = sB2 + (st)*2176 + rowB*136 + colB; cp16(d,bp); cp16(d+4,bp+4); }
    ST_A(0,kOff)    ST_B(0,kOff)    CP_COMMIT;
    ST_A(1,kOff+32) ST_B(1,kOff+32) CP_COMMIT;
    ST_A(2,kOff+64) ST_B(2,kOff+64) CP_COMMIT;

    for (int kt=0; kt<KT; kt++){
        CP_WAIT2;
        __syncthreads();
        if (kt+3 < KT){ int st=(kt+3)&3; int K0=kOff+(kt+3)*32; ST_A(st,K0) ST_B(st,K0) }
        CP_COMMIT;
        const int buf = kt&3;
        __half* sAb = sA + buf*4096;
        unsigned* sBb = sBu + buf*2176;
#pragma unroll
        for (int ks=0;ks<2;ks++){
            unsigned af[4][4], bf[4][2];
            LOAD_AF16(af, sAb, wm, ks, lane)
#pragma unroll
            for (int j=0;j<4;j++){
                int c = wn*32 + j*8 + gid;
                bf[j][0]=sBb[(ks*8+tig  )*136 + c];
                bf[j][1]=sBb[(ks*8+tig+4)*136 + c];
            }
#pragma unroll
            for (int i=0;i<4;i++)
#pragma unroll
                for (int j=0;j<4;j++) mma_f16(acc[i][j], af[i], bf[j]);
        }
    }
#undef ST_A
#undef ST_B

#pragma unroll
    for (int i=0;i<4;i++){
        int row = m0 + wm*64 + i*16 + gid;
        float* y0 = Y + (size_t)part*ELT_X + (size_t)(b*C_ + row)*T_;
        float* y8 = Y + (size_t)part*ELT_X + (size_t)(b*C_ + row+8)*T_;
#pragma unroll
        for (int j=0;j<4;j++){
            int col = n0 + wn*32 + j*8 + tig*2;
            *(float2*)(y0+col)=make_float2(acc[i][j][0], acc[i][j][1]);
            *(float2*)(y8+col)=make_float2(acc[i][j][2], acc[i][j][3]);
        }
    }
}

/* =========== fp16 fused Q/K/V ============ */
__launch_bounds__(256,2)
__global__ void g_qkv(const __half* __restrict__ X2h,
                      const __half* __restrict__ Wq, const __half* __restrict__ Wk, const __half* __restrict__ Wv,
                      const float* __restrict__ bq, const float* __restrict__ bk, const float* __restrict__ bv,
                      __half* __restrict__ Yq, __half* __restrict__ Yk, __half* __restrict__ Yv)
{
    extern __shared__ char smraw[];
    __half* sA = (__half*)smraw;
    __half2* sB2 = (__half2*)(smraw + 4*4096*2);
    unsigned* sBu = (unsigned*)sB2;
    const int n0 = blockIdx.x*128;
    const int mi = blockIdx.y;
    const int sel = mi >> 2;
    const int m0 = (mi & 3)*128;
    const int b  = blockIdx.z;
    const __half* Wm = (sel==0)?Wq:(sel==1)?Wk:Wv;
    const float* bias= (sel==0)?bq:(sel==1)?bk:bv;
    const float alpha= (sel==0)?0.125f:1.f;

    const int tid = threadIdx.x;
    const int lane = tid & 31, wid = tid >> 5;
    const int gid = lane >> 2, tig = lane & 3;
    const int wm = wid & 1, wn = wid >> 1;

    const __half2* X2 = (const __half2*)X2h + (size_t)b*256*T_;
    const int rowB = tid >> 4, colB = (tid & 15)*8;

    float acc[4][4][4];
#pragma unroll
    for (int i=0;i<4;i++)
#pragma unroll
        for (int j=0;j<4;j++)
#pragma unroll
            for (int u=0;u<4;u++) acc[i][j][u]=0.f;

    const int KT = C_/32;
#define ST_A(st,K0) { const __half* ap = Wm + (size_t)(m0>>7)*65536 + (size_t)((K0)>>5)*4096 + tid*16; \
                      __half* d = sA + (st)*4096 + tid*16; cp16(d,ap); cp16(d+8,ap+8); }
#define ST_B(st,K0) { const __half2* bp = X2 + (size_t)(((K0)>>1) + rowB)*T_ + n0 + colB; \
                      __half2* d = sB2 + (st)*2176 + rowB*136 + colB; cp16(d,bp); cp16(d+4,bp+4); }
    ST_A(0,0)  ST_B(0,0)  CP_COMMIT;
    ST_A(1,32) ST_B(1,32) CP_COMMIT;
    ST_A(2,64) ST_B(2,64) CP_COMMIT;

    for (int kt=0; kt<KT; kt++){
        CP_WAIT2;
        __syncthreads();
        if (kt+3 < KT){ int st=(kt+3)&3; int K0=(kt+3)*32; ST_A(st,K0) ST_B(st,K0) }
        CP_COMMIT;
        const int buf = kt&3;
        __half* sAb = sA + buf*4096;
        unsigned* sBb = sBu + buf*2176;
#pragma unroll
        for (int ks=0;ks<2;ks++){
            unsigned af[4][4], bf[4][2];
            LOAD_AF16(af, sAb, wm, ks, lane)
#pragma unroll
            for (int j=0;j<4;j++){
                int c = wn*32 + j*8 + gid;
                bf[j][0]=sBb[(ks*8+tig  )*136 + c];
                bf[j][1]=sBb[(ks*8+tig+4)*136 + c];
            }
#pragma unroll
            for (int i=0;i<4;i++)
#pragma unroll
                for (int j=0;j<4;j++) mma_f16(acc[i][j], af[i], bf[j]);
        }
    }
#undef ST_A
#undef ST_B

#pragma unroll
    for (int i=0;i<4;i++){
        int row = m0 + wm*64 + i*16 + gid;
        float bv0 = bias[row], bv8 = bias[row+8];
        int h0 = row>>6, dv = row&63;
        if (sel==0){
            __half* base = Yq + (size_t)(b*H_+h0)*T_*64;
#pragma unroll
            for (int j=0;j<4;j++){
                int col = n0 + wn*32 + j*8 + tig*2;
                base[(size_t)col*64 + dv]        = __float2half_rn(alpha*(acc[i][j][0]+bv0));
                base[(size_t)(col+1)*64 + dv]    = __float2half_rn(alpha*(acc[i][j][1]+bv0));
                base[(size_t)col*64 + dv+8]      = __float2half_rn(alpha*(acc[i][j][2]+bv8));
                base[(size_t)(col+1)*64 + dv+8]  = __float2half_rn(alpha*(acc[i][j][3]+bv8));
            }
        } else if (sel==1){
            __half* base = Yk + (size_t)(b*H_+h0)*32*T_*2;
#pragma unroll
            for (int j=0;j<4;j++){
                int col = n0 + wn*32 + j*8 + tig*2;
                base[(((size_t)(dv>>1))*T_ + col)*2 + (dv&1)]       = __float2half_rn(acc[i][j][0]+bv0);
                base[(((size_t)(dv>>1))*T_ + col+1)*2 + (dv&1)]     = __float2half_rn(acc[i][j][1]+bv0);
                base[(((size_t)((dv+8)>>1))*T_ + col)*2 + (dv&1)]   = __float2half_rn(acc[i][j][2]+bv8);
                base[(((size_t)((dv+8)>>1))*T_ + col+1)*2 + (dv&1)] = __float2half_rn(acc[i][j][3]+bv8);
            }
        } else {
            __half* base = Yv + (size_t)(b*H_+h0)*256*64*2;
#pragma unroll
            for (int j=0;j<4;j++){
                int col = n0 + wn*32 + j*8 + tig*2;
                base[(((size_t)(col>>1))*64 + dv)*2 + 0]   = __float2half_rn(acc[i][j][0]+bv0);
                base[(((size_t)(col>>1))*64 + dv)*2 + 1]   = __float2half_rn(acc[i][j][1]+bv0);
                base[(((size_t)(col>>1))*64 + dv+8)*2 + 0] = __float2half_rn(acc[i][j][2]+bv8);
                base[(((size_t)(col>>1))*64 + dv+8)*2 + 1] = __float2half_rn(acc[i][j][3]+bv8);
            }
        }
    }
}

/* =========== fp16 scores: P = Qh @ Kh, out fp32 ============ */
__launch_bounds__(256,2)
__global__ void g_sc(const __half* __restrict__ Qh, const __half* __restrict__ Kh,
                     float* __restrict__ P)
{
    extern __shared__ char smraw[];
    __half* sA = (__half*)smraw;
    unsigned* sBu = (unsigned*)(smraw + 4*5120*2);
    const int s0 = blockIdx.x*128;
    const int t0 = blockIdx.y*128;
    const int bh = blockIdx.z;
    const int tid = threadIdx.x;
    const int lane = tid & 31, wid = tid >> 5;
    const int gid = lane >> 2, tig = lane & 3;
    const int wm = wid & 1, wn = wid >> 1;

    const __half* qb = Qh + (size_t)bh*T_*64;
    const __half2* kb = (const __half2*)Kh + (size_t)bh*32*T_;
    const int rowA = tid >> 1, colA = (tid & 1)*16;
    const int rowB = tid >> 4, colB = (tid & 15)*8;

    float acc[4][4][4];
#pragma unroll
    for (int i=0;i<4;i++)
#pragma unroll
        for (int j=0;j<4;j++)
#pragma unroll
            for (int u=0;u<4;u++) acc[i][j][u]=0.f;

#define ST_A(st,K0) { const __half* ap = qb + (size_t)(t0+rowA)*64 + (K0) + colA; \
                      __half* d = sA + (st)*5120 + rowA*40 + colA; cp16(d,ap); cp16(d+8,ap+8); }
#define ST_B(st,K0) { const __half2* bp = kb + (size_t)(((K0)>>1)+rowB)*T_ + s0 + colB; \
                      __half2* d = (__half2*)sBu + (size_t)(st)*2176 + rowB*136 + colB; \
                      cp16(d,bp); cp16(d+4,bp+4); }
    ST_A(0,0)  ST_B(0,0)  CP_COMMIT;
    ST_A(1,32) ST_B(1,32) CP_COMMIT;
    CP_COMMIT;

    for (int kt=0; kt<2; kt++){
        CP_WAIT2;
        __syncthreads();
        CP_COMMIT;
        const int buf = kt;
        __half* sAb = sA + buf*5120;
        unsigned* sBb = sBu + buf*2176;
#pragma unroll
        for (int ks=0;ks<2;ks++){
            unsigned af[4][4], bf[4][2];
#pragma unroll
            for (int i=0;i<4;i++){
                int r = wm*64 + i*16 + gid;
                af[i][0]=*(const unsigned*)(sAb + (size_t)r*40 + ks*16 + tig*2);
                af[i][1]=*(const unsigned*)(sAb + (size_t)(r+8)*40 + ks*16 + tig*2);
                af[i][2]=*(const unsigned*)(sAb + (size_t)r*40 + ks*16 + tig*2 + 8);
                af[i][3]=*(const unsigned*)(sAb + (size_t)(r+8)*40 + ks*16 + tig*2 + 8);
            }
#pragma unroll
            for (int j=0;j<4;j++){
                int c = wn*32 + j*8 + gid;
                bf[j][0]=sBb[(ks*8+tig  )*136 + c];
                bf[j][1]=sBb[(ks*8+tig+4)*136 + c];
            }
#pragma unroll
            for (int i=0;i<4;i++)
#pragma unroll
                for (int j=0;j<4;j++) mma_f16(acc[i][j], af[i], bf[j]);
        }
    }
#undef ST_A
#undef ST_B

#pragma unroll
    for (int i=0;i<4;i++){
        int row = t0 + wm*64 + i*16 + gid;
        float* y0 = P + ((size_t)bh*T_ + row)*T_;
        float* y8 = P + ((size_t)bh*T_ + row+8)*T_;
#pragma unroll
        for (int j=0;j<4;j++){
            int col = s0 + wn*32 + j*8 + tig*2;
            *(float2*)(y0+col)=make_float2(acc[i][j][0], acc[i][j][1]);
            *(float2*)(y8+col)=make_float2(acc[i][j][2], acc[i][j][3]);
        }
    }
}

/* =========== fp16 ctx: Ph @ Vh + rel-V band -> hC packed fp16 ============ */
__launch_bounds__(256,2)
__global__ void g_ctx(const __half* __restrict__ Ph, const __half* __restrict__ Vh,
                      const float* __restrict__ erv, __half* __restrict__ Ch)
{
    extern __shared__ char smraw[];
    __half* sA = (__half*)smraw;
    unsigned* sBu = (unsigned*)(smraw + 4*5120*2);
    float* sErv = (float*)(smraw + 4*5120*2 + 4*1152*4);
    const int t0 = blockIdx.x*128;
    const int bh = blockIdx.y;
    const int b  = bh >> 3, h = bh & 7;
    const int tid = threadIdx.x;
    const int lane = tid & 31, wid = tid >> 5;
    const int gid = lane >> 2, tig = lane & 3;
    const int wm = wid & 1, wn = wid >> 1;

    const __half* pb = Ph + (size_t)bh*T_*T_;
    const __half2* vb = (const __half2*)Vh + (size_t)bh*256*64;
    const int rowA = tid >> 1, colA = (tid & 1)*16;
    const int rowB = tid >> 4, colB = (tid & 15)*4;

    for (int l=tid; l<21*64; l+=256) sErv[l]=erv[l];

    float acc[4][2][4];
#pragma unroll
    for (int i=0;i<4;i++)
#pragma unroll
        for (int j=0;j<2;j++)
#pragma unroll
            for (int u=0;u<4;u++) acc[i][j][u]=0.f;

#define ST_A(st,K0) { const __half* ap = pb + (size_t)(t0+rowA)*T_ + (K0) + colA; \
                      __half* d = sA + (st)*5120 + rowA*40 + colA; cp16(d,ap); cp16(d+8,ap+8); }
#define ST_B(st,K0) { const __half2* bp = vb + (size_t)(((K0)>>1)+rowB)*64 + colB; \
                      __half2* d = (__half2*)sBu + (size_t)(st)*1152 + rowB*72 + colB; cp16(d,bp); }
    ST_A(0,0)  ST_B(0,0)  CP_COMMIT;
    ST_A(1,32) ST_B(1,32) CP_COMMIT;
    ST_A(2,64) ST_B(2,64) CP_COMMIT;

    const int KT = T_/32;
    for (int kt=0; kt<KT; kt++){
        CP_WAIT2;
        __syncthreads();
        if (kt+3 < KT){ int st=(kt+3)&3; int K0=(kt+3)*32; ST_A(st,K0) ST_B(st,K0) }
        CP_COMMIT;
        const int buf = kt&3;
        __half* sAb = sA + buf*5120;
        unsigned* sBb = sBu + buf*1152;
#pragma unroll
        for (int ks=0;ks<2;ks++){
            unsigned af[4][4], bf[2][2];
#pragma unroll
            for (int i=0;i<4;i++){
                int r = wm*64 + i*16 + gid;
                af[i][0]=*(const unsigned*)(sAb + (size_t)r*40 + ks*16 + tig*2);
                af[i][1]=*(const unsigned*)(sAb + (size_t)(r+8)*40 + ks*16 + tig*2);
                af[i][2]=*(const unsigned*)(sAb + (size_t)r*40 + ks*16 + tig*2 + 8);
                af[i][3]=*(const unsigned*)(sAb + (size_t)(r+8)*40 + ks*16 + tig*2 + 8);
            }
#pragma unroll
            for (int j=0;j<2;j++){
                int c = wn*16 + j*8 + gid;
                bf[j][0]=sBb[(ks*8+tig  )*72 + c];
                bf[j][1]=sBb[(ks*8+tig+4)*72 + c];
            }
#pragma unroll
            for (int i=0;i<4;i++)
#pragma unroll
                for (int j=0;j<2;j++) mma_f16(acc[i][j], af[i], bf[j]);
        }
    }
#undef ST_A
#undef ST_B

#pragma unroll
    for (int i=0;i<4;i++){
#pragma unroll
        for (int rr=0; rr<2; rr++){
            int t = t0 + wm*64 + i*16 + gid + rr*8;
            const __half* prow = pb + (size_t)t*T_;
            for (int r=0;r<21;r++){
                int s = t + r - WIN_;
                if ((unsigned)s < (unsigned)T_){
                    float pv = __half2float(prow[s]);
#pragma unroll
                    for (int j=0;j<2;j++){
                        int d = wn*16 + j*8 + tig*2;
                        acc[i][j][rr*2+0] += pv*sErv[r*64 + d];
                        acc[i][j][rr*2+1] += pv*sErv[r*64 + d+1];
                    }
                }
            }
        }
    }

    __half2* C2 = (__half2*)Ch;
#pragma unroll
    for (int i=0;i<4;i++){
        int row = t0 + wm*64 + i*16 + gid;
#pragma unroll
        for (int j=0;j<2;j++){
            int c = h*64 + wn*16 + j*8 + tig*2;
            __half2* cp = C2 + (size_t)(b*256 + (c>>1))*T_;
            cp[row]   = __floats2half2_rn(acc[i][j][0], acc[i][j][1]);
            cp[row+8] = __floats2half2_rn(acc[i][j][2], acc[i][j][3]);
        }
    }
}

/* =========== fp16 K=3 conv as 3 tap-GEMMs =========== */
__launch_bounds__(256,2)
__global__ void gconv3p(const __half* __restrict__ Xp, const __half* __restrict__ Wc,
                        const float* __restrict__ bias, const float* __restrict__ mask,
                        float* __restrict__ Y, __half* __restrict__ Yh,
                        int Cin, int Cout, int mode, int ktiles)
{
    extern __shared__ char smraw[];
    __half* sA = (__half*)smraw;
    __half* sX = (__half*)(smraw + 4*6144*2);
    const int n0 = blockIdx.x*128;
    const int m0 = blockIdx.y*128;
    const int bz = blockIdx.z;
    const int b    = (mode==1) ? (bz & 7) : bz;
    const int part = (mode==1) ? (bz >> 3) : 0;
    const int kOff16 = part*ktiles;

    const int tid = threadIdx.x;
    const int lane = tid & 31, wid = tid >> 5;
    const int gid = lane >> 2, tig = lane & 3;
    const int wm = wid & 1, wn = wid >> 1;

    const __half* xb = Xp + (size_t)b*516*Cin;
    const size_t wmt = (size_t)(m0>>7)*((size_t)Cin*384);

    float acc[4][4][4];
#pragma unroll
    for (int i=0;i<4;i++)
#pragma unroll
        for (int j=0;j<4;j++)
#pragma unroll
            for (int u=0;u<4;u++) acc[i][j][u]=0.f;

#define ST_A(st,ct) { const __half* ap = Wc + wmt + (size_t)(ct)*6144 + tid*24; \
                      __half* d = sA + (st)*6144 + tid*24; \
                      cp16(d,ap); cp16(d+8,ap+8); cp16(d+16,ap+16); }
#define ST_B(st,ct) { int c0 = (ct)*16; \
                      { int r = tid>>1, q = tid&1; \
                        const __half* bp = xb + (size_t)(n0 + r)*Cin + c0 + q*8; \
                        cp16(sX + (st)*3120 + r*24 + q*8, bp); } \
                      { int slot = tid+256; if (slot < 260){ int r = slot>>1, q = slot&1; \
                        const __half* bp = xb + (size_t)(n0 + r)*Cin + c0 + q*8; \
                        cp16(sX + (st)*3120 + r*24 + q*8, bp); } } }
    if (0 < ktiles){ ST_A(0,kOff16)   ST_B(0,kOff16)   } CP_COMMIT;
    if (1 < ktiles){ ST_A(1,kOff16+1) ST_B(1,kOff16+1) } CP_COMMIT;
    if (2 < ktiles){ ST_A(2,kOff16+2) ST_B(2,kOff16+2) } CP_COMMIT;

    for (int kt=0; kt<ktiles; kt++){
        CP_WAIT2;
        __syncthreads();
        if (kt+3 < ktiles){ int st=(kt+3)&3; int ct=kOff16+kt+3; ST_A(st,ct) ST_B(st,ct) }
        CP_COMMIT;
        const int buf = kt&3;
        const __half* sAb = sA + buf*6144;
        const unsigned* sXu = (const unsigned*)(sX + buf*3120);
#pragma unroll
        for (int tap=0; tap<3; tap++){
            unsigned af[4][4], bf[4][2];
#pragma unroll
            for (int i=0;i<4;i++){
                const float4 av = *(const float4*)(sAb + tap*2048 + ((wm*4+i)*32 + lane)*8);
                af[i][0]=__float_as_uint(av.x); af[i][1]=__float_as_uint(av.y);
                af[i][2]=__float_as_uint(av.z); af[i][3]=__float_as_uint(av.w);
            }
#pragma unroll
            for (int j=0;j<4;j++){
                int rrow = wn*32 + j*8 + gid + tap;
                bf[j][0]=sXu[rrow*12 + tig    ];
                bf[j][1]=sXu[rrow*12 + tig + 4];
            }
#pragma unroll
            for (int i=0;i<4;i++)
#pragma unroll
                for (int j=0;j<4;j++) mma_f16(acc[i][j], af[i], bf[j]);
        }
    }
#undef ST_A
#undef ST_B

    if (mode==0){
        const float* mb = mask + b*T_;
#pragma unroll
        for (int i=0;i<4;i++){
            int row = m0 + wm*64 + i*16 + gid;
            float bv0 = bias[row], bv8 = bias[row+8];
#pragma unroll
            for (int j=0;j<4;j++){
                int col = n0 + wn*32 + j*8 + tig*2;
                float m0v = mb[col], m1v = mb[col+1];
                __half* p0 = Yh + (size_t)(b*516 + col+1)*F_;
                __half* p1 = Yh + (size_t)(b*516 + col+2)*F_;
                p0[row]   = __float2half_rn(fmaxf(acc[i][j][0]+bv0, 0.f)*m0v);
                p1[row]   = __float2half_rn(fmaxf(acc[i][j][1]+bv0, 0.f)*m1v);
                p0[row+8] = __float2half_rn(fmaxf(acc[i][j][2]+bv8, 0.f)*m0v);
                p1[row+8] = __float2half_rn(fmaxf(acc[i][j][3]+bv8, 0.f)*m1v);
            }
        }
    } else {
#pragma unroll
        for (int i=0;i<4;i++){
            int row = m0 + wm*64 + i*16 + gid;
            float* y0 = Y + (size_t)part*ELT_X + (size_t)(b*Cout + row)*T_;
            float* y8 = Y + (size_t)part*ELT_X + (size_t)(b*Cout + row+8)*T_;
#pragma unroll
            for (int j=0;j<4;j++){
                int col = n0 + wn*32 + j*8 + tig*2;
                *(float2*)(y0+col)=make_float2(acc[i][j][0], acc[i][j][1]);
                *(float2*)(y8+col)=make_float2(acc[i][j][2], acc[i][j][3]);
            }
        }
    }
}

/* ---- fused softmax: parallel band(q·erk) + mask + softmax; fp32 in, fp16 out ---- */
__launch_bounds__(256)
__global__ void k_softmax(const float* __restrict__ P, const float* __restrict__ mask,
                          const __half* __restrict__ Qh, const float* __restrict__ erk,
                          __half* __restrict__ Ph)
{
    const int row = blockIdx.x;
    const int t  = row & (T_-1);
    const int bh = row >> 9;
    const int b  = bh >> 3;
    const float* p = P + (size_t)row*T_;
    __half* ph = Ph + (size_t)row*T_;
    const float* mb = mask + b*T_;
    const int tid = threadIdx.x;
    const int lane = tid & 31, w = tid >> 5;

    __shared__ float band[24];
    {
        const __half* qr = Qh + ((size_t)bh*T_ + t)*64;
        float q0 = __half2float(qr[lane]);
        float q1 = __half2float(qr[32+lane]);
        for (int r = w; r < 21; r += 8){
            float s = q0*erk[r*64+lane] + q1*erk[r*64+32+lane];
#pragma unroll
            for (int o=16;o;o>>=1) s += __shfl_xor_sync(0xffffffffu, s, o);
            if (lane==0) band[r] = s;
        }
    }
    __syncthreads();

    const float mt = mb[t];
    int r0 = tid - t + WIN_;
    int r1 = tid + 256 - t + WIN_;
    float p0 = p[tid]     + (((unsigned)r0 < 21u) ? band[r0] : 0.f);
    float p1 = p[tid+256] + (((unsigned)r1 < 21u) ? band[r1] : 0.f);
    float v0 = (mt*mb[tid]     != 0.f) ? p0 : -1e4f;
    float v1 = (mt*mb[tid+256] != 0.f) ? p1 : -1e4f;
    __shared__ float red[8];
    float m = fmaxf(v0,v1);
#pragma unroll
    for (int o=16;o;o>>=1) m = fmaxf(m, __shfl_xor_sync(0xffffffffu, m, o));
    if (lane==0) red[w]=m;
    __syncthreads();
    float mx = red[0];
#pragma unroll
    for (int k2=1;k2<8;k2++) mx = fmaxf(mx, red[k2]);
    float e0 = expf(v0-mx), e1 = expf(v1-mx);
    float s = e0+e1;
#pragma unroll
    for (int o=16;o;o>>=1) s += __shfl_xor_sync(0xffffffffu, s, o);
    __syncthreads();
    if (lane==0) red[w]=s;
    __syncthreads();
    float tot = 0.f;
#pragma unroll
    for (int k2=0;k2<8;k2++) tot += red[k2];
    float inv = 1.f/tot;
    ph[tid]     = __float2half_rn(e0*inv);
    ph[tid+256] = __float2half_rn(e1*inv);
}

/* ---- fused: g1x1 split-K reduce + bias + residual + LN; emits padded fp16 x ---- */
__launch_bounds__(512)
__global__ void k_addln(float* __restrict__ X, const float* __restrict__ P0,
                        const float* __restrict__ bias1,
                        const float* __restrict__ gamma, const float* __restrict__ beta,
                        __half* __restrict__ Xp, const float* __restrict__ mask)
{
    const int b = blockIdx.y;
    const int tl = threadIdx.x & 31;
    const int slot = threadIdx.x >> 5;
    const int t = blockIdx.x*32 + tl;
    __shared__ float ssum[16][33];
    __shared__ float ssq[16][33];
    float vals[32];
    float s=0.f, q=0.f;
    size_t base = (size_t)b*C_*T_ + t;
#pragma unroll
    for (int u=0;u<32;u++){
        int c = slot*32+u;
        size_t idx = base + (size_t)c*T_;
        float y = P0[idx] + P0[(size_t)ELT_X + idx] + bias1[c];
        float v = X[idx] + y;
        vals[u]=v; s+=v; q+=v*v;
    }
    ssum[slot][tl]=s; ssq[slot][tl]=q;
    __syncthreads();
    float m=0.f, vv=0.f;
#pragma unroll
    for (int k2=0;k2<16;k2++){ m+=ssum[k2][tl]; vv+=ssq[k2][tl]; }
    m *= (1.f/512.f);
    vv = vv*(1.f/512.f) - m*m;
    float r = rsqrtf(vv + 1e-5f);
    float mk = mask[b*T_ + t];
#pragma unroll
    for (int u=0;u<32;u++){
        int c = slot*32+u;
        float o = (vals[u]-m)*r*gamma[c] + beta[c];
        X[base + (size_t)c*T_] = o;
        Xp[(size_t)(b*516 + t+1)*C_ + c] = __float2half_rn(o*mk);
    }
}

/* ---- fused: conv split-K reduce + bias + mask + residual + LN; emits packed-pair fp16 */
__launch_bounds__(512)
__global__ void k_addln2(float* __restrict__ X, const float* __restrict__ P0,
                         const float* __restrict__ bias2,
                         const float* __restrict__ gamma, const float* __restrict__ beta,
                         __half* __restrict__ Xr, const float* __restrict__ mask)
{
    const int b = blockIdx.y;
    const int tl = threadIdx.x & 31;
    const int slot = threadIdx.x >> 5;
    const int t = blockIdx.x*32 + tl;
    __shared__ float ssum[16][33];
    __shared__ float ssq[16][33];
    float vals[32];
    float s=0.f, q=0.f;
    size_t base = (size_t)b*C_*T_ + t;
    const float mk = mask[b*T_ + t];
#pragma unroll
    for (int u=0;u<32;u++){
        int c = slot*32+u;
        size_t idx = base + (size_t)c*T_;
        float y = (P0[idx] + P0[(size_t)ELT_X + idx] + bias2[c]) * mk;
        float v = X[idx] + y;
        vals[u]=v; s+=v; q+=v*v;
    }
    ssum[slot][tl]=s; ssq[slot][tl]=q;
    __syncthreads();
    float m=0.f, vv=0.f;
#pragma unroll
    for (int k2=0;k2<16;k2++){ m+=ssum[k2][tl]; vv+=ssq[k2][tl]; }
    m *= (1.f/512.f);
    vv = vv*(1.f/512.f) - m*m;
    float r = rsqrtf(vv + 1e-5f);
#pragma unroll
    for (int u=0;u<32;u++){
        int c = slot*32+u;
        float o = (vals[u]-m)*r*gamma[c] + beta[c];
        X[base + (size_t)c*T_] = o;
        Xr[((size_t)(b*256 + (c>>1))*T_ + t)*2 + (c&1)] = __float2half_rn(o);
    }
}

/* ---------------- host orchestration ---------------- */
extern "C" void kernel_launch(void* const* d_in, const int* in_sizes, int n_in,
                              void* d_out, int out_size)
{
    (void)in_sizes; (void)n_in; (void)out_size;
    const float* x_in = (const float*)d_in[0];
    const float* mask = (const float*)d_in[1];
    const float* Wq  = (const float*)d_in[2];
    const float* bq  = (const float*)d_in[3];
    const float* Wk  = (const float*)d_in[4];
    const float* bk  = (const float*)d_in[5];
    const float* Wv  = (const float*)d_in[6];
    const float* bv  = (const float*)d_in[7];
    const float* Wo  = (const float*)d_in[8];
    const float* bo  = (const float*)d_in[9];
    const float* erk = (const float*)d_in[10];
    const float* erv = (const float*)d_in[11];
    const float* g1  = (const float*)d_in[12];
    const float* b1  = (const float*)d_in[13];
    const float* g2  = (const float*)d_in[14];
    const float* b2  = (const float*)d_in[15];
    const float* W1  = (const float*)d_in[16];
    const float* bf1 = (const float*)d_in[17];
    const float* W2  = (const float*)d_in[18];
    const float* bf2 = (const float*)d_in[19];

    const int SM_GW  = 4*(4096 + 2176*2)*2;
    const int SM_SC  = 4*5120*2 + 4*2176*4;
    const int SM_CTX = 4*5120*2 + 4*1152*4 + 21*64*4;
    const int SM_CV  = 4*(6144 + 3120)*2;
    cudaFuncSetAttribute(g1x1,   cudaFuncAttributeMaxDynamicSharedMemorySize, SM_GW);
    cudaFuncSetAttribute(g_qkv,  cudaFuncAttributeMaxDynamicSharedMemorySize, SM_GW);
    cudaFuncSetAttribute(g_sc,   cudaFuncAttributeMaxDynamicSharedMemorySize, SM_SC);
    cudaFuncSetAttribute(g_ctx,  cudaFuncAttributeMaxDynamicSharedMemorySize, SM_CTX);
    cudaFuncSetAttribute(gconv3p,cudaFuncAttributeMaxDynamicSharedMemorySize, SM_CV);

    float* pool = 0;
    cudaGetSymbolAddress((void**)&pool, g_pool);
    float* px = pool;
    float* pq = pool + (size_t)1*ELT_X;   /* split-K partials (slots 1,2) */
    float* pp = pool + (size_t)4*ELT_X;   /* scores fp32 (ELT_P) */
    __half* hb  = (__half*)(pool + (size_t)4*ELT_X + ELT_P + ELT_X);
    __half* hXr  = hb;
    __half* hC   = hXr + (size_t)ELT_X;
    __half* hXp1 = hC  + (size_t)ELT_X;
    __half* hXp2 = hXp1 + (size_t)B_*516*C_;
    __half* hWq  = hXp2 + (size_t)B_*516*F_;
    __half* hWk  = hWq + WQKV;
    __half* hWv  = hWk + WQKV;
    __half* hWo  = hWv + WQKV;
    __half* hW1  = hWo + WQKV;
    __half* hW2  = hW1 + WFF;
    __half* hQ   = hW2 + WFF;
    __half* hK   = hQ + (size_t)ELT_X;
    __half* hV   = hK + (size_t)ELT_X;
    __half* hP   = hV + (size_t)ELT_X;

    size_t mszQ = (size_t)C_*C_;
    k_swizA16<<<(unsigned)((WQKV+255)/256),256>>>(Wq, hWq, C_, mszQ, WQKV);
    k_swizA16<<<(unsigned)((WQKV+255)/256),256>>>(Wk, hWk, C_, mszQ, WQKV);
    k_swizA16<<<(unsigned)((WQKV+255)/256),256>>>(Wv, hWv, C_, mszQ, WQKV);
    k_swizA16<<<(unsigned)((WQKV+255)/256),256>>>(Wo, hWo, C_, mszQ, WQKV);
    k_swizC16<<<(unsigned)((WFF+255)/256),256>>>(W1, hW1, C_, (size_t)F_*C_*3, WFF);
    k_swizC16<<<(unsigned)((WFF+255)/256),256>>>(W2, hW2, F_, (size_t)C_*F_*3, WFF);

    k_maskmul2<<<ELT_X/256,256>>>(x_in, mask, px, hXr);
    k_zb16<<<20480/256,256>>>(hXp1, hXp2);

    for (int L=0;L<6;L++){
        g_qkv<<<dim3(T_/128, 12, B_),256,SM_GW>>>(hXr, hWq + L*mszQ, hWk + L*mszQ, hWv + L*mszQ,
                                                  bq+L*C_, bk+L*C_, bv+L*C_, hQ, hK, hV);
        g_sc<<<dim3(T_/128, T_/128, B_*H_),256,SM_SC>>>(hQ, hK, pp);
        k_softmax<<<B_*H_*T_,256>>>(pp, mask, hQ, erk + L*21*64, hP);
        g_ctx<<<dim3(T_/128, B_*H_),256,SM_CTX>>>(hP, hV, erv + L*21*64, hC);
        g1x1<<<dim3(T_/128, C_/128, 2*B_),256,SM_GW>>>(hWo + L*mszQ, hC, pq);
        k_addln<<<dim3(T_/32,B_),512>>>(px, pq, bo+L*C_, g1+L*C_, b1+L*C_, hXp1, mask);

        gconv3p<<<dim3(T_/128, F_/128, B_),256,SM_CV>>>(hXp1, hW1 + (size_t)L*F_*C_*3,
                                                        bf1+L*F_, mask, (float*)0, hXp2,
                                                        C_, F_, 0, C_/16);
        gconv3p<<<dim3(T_/128, C_/128, 2*B_),256,SM_CV>>>(hXp2, hW2 + (size_t)L*C_*F_*3,
                                                          bf2+L*C_, mask, pq, (__half*)0,
                                                          F_, C_, 1, F_/32);
        k_addln2<<<dim3(T_/32,B_),512>>>(px, pq, bf2+L*C_, g2+L*C_, b2+L*C_, hXr, mask);
    }
    k_maskmul<<<ELT_X/256,256>>>(px, mask, (float*)d_out);
}

// round 16
// speedup vs baseline: 1.0164x; 1.0164x over previous
#include <cuda_runtime.h>
#include <cuda_fp16.h>
#include <math.h>

#define B_ 8
#define T_ 512
#define C_ 512
#define H_ 8
#define F_ 2048
#define WIN_ 10

#define ELT_X (B_*C_*T_)
#define ELT_P (B_*H_*T_*T_)
#define WQKV ((size_t)6*C_*C_)
#define WFF  ((size_t)6*F_*C_*3)

#define HALFS ((size_t)5*ELT_X + (size_t)B_*516*(C_+F_) + 4*WQKV + 2*WFF + ELT_P)
__device__ float g_pool[(size_t)5*ELT_X + ELT_P + (HALFS+1)/2];

__device__ __forceinline__ void mma_f16(float c[4], const unsigned a[4], const unsigned b[2]){
    asm("mma.sync.aligned.m16n8k16.row.col.f32.f16.f16.f32 "
        "{%0,%1,%2,%3}, {%4,%5,%6,%7}, {%8,%9}, {%0,%1,%2,%3};"
        : "+f"(c[0]), "+f"(c[1]), "+f"(c[2]), "+f"(c[3])
        : "r"(a[0]), "r"(a[1]), "r"(a[2]), "r"(a[3]), "r"(b[0]), "r"(b[1]));
}
__device__ __forceinline__ void cp16(void* smem, const void* g){
    unsigned s = (unsigned)__cvta_generic_to_shared(smem);
    asm volatile("cp.async.ca.shared.global [%0], [%1], 16;" :: "r"(s), "l"(g));
}
#define CP_COMMIT asm volatile("cp.async.commit_group;" ::: "memory")
#define CP_WAIT2  asm volatile("cp.async.wait_group 2;" ::: "memory")

/* ===== fp16 dense weight swizzle ===== */
__global__ void k_swizA16(const float* __restrict__ S, __half* __restrict__ D,
                          int Ktot, size_t msz, size_t total)
{
    size_t idx = (size_t)blockIdx.x*256 + threadIdx.x;
    if (idx >= total) return;
    size_t l = idx / msz;
    size_t od = idx - l*msz;
    int mtile = (int)(od / ((size_t)Ktot*128));
    int rem = (int)(od - (size_t)mtile*Ktot*128);
    int ktile = rem >> 12;
    int rem2 = rem & 4095;
    int mgrp = rem2 >> 9;
    int rem3 = rem2 & 511;
    int ks = rem3 >> 8;
    int rem4 = rem3 & 255;
    int lane = rem4 >> 3;
    int u = rem4 & 7;
    int reg = u >> 1, hh = u & 1;
    int gid = lane >> 2, tig = lane & 3;
    int m = mtile*128 + mgrp*16 + gid + (reg&1)*8;
    int k = ktile*32 + ks*16 + tig*2 + hh + (reg>>1)*8;
    D[idx] = __float2half_rn(S[l*msz + (size_t)m*Ktot + k]);
}

/* ===== fp16 conv weight swizzle ===== */
__global__ void k_swizC16(const float* __restrict__ S, __half* __restrict__ D,
                          int Cin, size_t msz3, size_t total)
{
    size_t idx = (size_t)blockIdx.x*256 + threadIdx.x;
    if (idx >= total) return;
    size_t l = idx / msz3;
    size_t od = idx - l*msz3;
    int mtile = (int)(od / ((size_t)Cin*384));
    int rem = (int)(od - (size_t)mtile*Cin*384);
    int ctile = rem / 6144;
    int rem2 = rem % 6144;
    int tap = rem2 >> 11;
    int rem3 = rem2 & 2047;
    int mgrp = rem3 >> 8;
    int rem4 = rem3 & 255;
    int lane = rem4 >> 3;
    int u = rem4 & 7;
    int reg = u >> 1, hh = u & 1;
    int gid = lane >> 2, tig = lane & 3;
    int m = mtile*128 + mgrp*16 + gid + (reg&1)*8;
    int c = ctile*16 + tig*2 + hh + (reg>>1)*8;
    D[idx] = __float2half_rn(S[l*msz3 + (size_t)m*Cin*3 + (size_t)c*3 + tap]);
}

/* ---- mask: px fp32 + hXr packed-pair fp16 ---- */
__global__ void k_maskmul2(const float* __restrict__ X, const float* __restrict__ mask,
                           float* __restrict__ Y, __half* __restrict__ Xr)
{
    int i = blockIdx.x*256 + threadIdx.x;
    int t = i & (T_-1);
    int c = (i >> 9) & (C_-1);
    int b = i >> 18;
    float v = X[i] * mask[b*T_ + t];
    Y[i] = v;
    Xr[((size_t)(b*256 + (c>>1))*T_ + t)*2 + (c&1)] = __float2half_rn(v);
}
__global__ void k_maskmul(const float* __restrict__ X, const float* __restrict__ mask,
                          float* __restrict__ Y)
{
    int i = blockIdx.x*256 + threadIdx.x;
    int t = i & (T_-1);
    int b = i / (C_*T_);
    Y[i] = X[i] * mask[b*T_ + t];
}

/* ---- zero border rows of hXp1 / hXp2 ---- */
__global__ void k_zb16(__half* __restrict__ Xp1, __half* __restrict__ Xp2)
{
    int idx2 = blockIdx.x*256 + threadIdx.x;
    if (idx2 < 4096){
        int b = idx2 >> 9, rr = (idx2 >> 8) & 1, off = idx2 & 255;
        ((__half2*)Xp1)[((size_t)(b*516 + rr*513)*C_)/2 + off] = __half2half2(__float2half(0.f));
    } else {
        int j = idx2 - 4096;
        int b = j >> 11, rr = (j >> 10) & 1, off = j & 1023;
        ((__half2*)Xp2)[((size_t)(b*516 + rr*513)*F_)/2 + off] = __half2half2(__float2half(0.f));
    }
}

#define LOAD_AF16(af, sAh, wm, ks1, lane) \
    _Pragma("unroll") \
    for (int i=0;i<4;i++){ \
        const float4 av = *(const float4*)((sAh) + ((((wm)*4+i)*2+(ks1))*32 + (lane))*8); \
        af[i][0]=__float_as_uint(av.x); af[i][1]=__float_as_uint(av.y); \
        af[i][2]=__float_as_uint(av.z); af[i][3]=__float_as_uint(av.w); \
    }

/* =========== fp16 1x1 GEMM (Wo), full-K, bias in epilogue ============ */
__launch_bounds__(256,2)
__global__ void g1x1(const __half* __restrict__ Wm, const __half* __restrict__ X2h,
                     const float* __restrict__ bias, float* __restrict__ Y)
{
    extern __shared__ char smraw[];
    __half* sA = (__half*)smraw;
    __half2* sB2 = (__half2*)(smraw + 4*4096*2);
    unsigned* sBu = (unsigned*)sB2;
    const int n0 = blockIdx.x*128;
    const int m0 = blockIdx.y*128;
    const int b  = blockIdx.z;
    const int tid = threadIdx.x;
    const int lane = tid & 31, wid = tid >> 5;
    const int gid = lane >> 2, tig = lane & 3;
    const int wm = wid & 1, wn = wid >> 1;

    const __half2* X2 = (const __half2*)X2h + (size_t)b*256*T_;
    const int rowB = tid >> 4, colB = (tid & 15)*8;

    float acc[4][4][4];
#pragma unroll
    for (int i=0;i<4;i++)
#pragma unroll
        for (int j=0;j<4;j++)
#pragma unroll
            for (int u=0;u<4;u++) acc[i][j][u]=0.f;

    const int KT = C_/32;
#define ST_A(st,K0) { const __half* ap = Wm + (size_t)(m0>>7)*65536 + (size_t)((K0)>>5)*4096 + tid*16; \
                      __half* d = sA + (st)*4096 + tid*16; cp16(d,ap); cp16(d+8,ap+8); }
#define ST_B(st,K0) { const __half2* bp = X2 + (size_t)(((K0)>>1) + rowB)*T_ + n0 + colB; \
                      __half2* d = sB2 + (st)*2176 + rowB*136 + colB; cp16(d,bp); cp16(d+4,bp+4); }
    ST_A(0,0)  ST_B(0,0)  CP_COMMIT;
    ST_A(1,32) ST_B(1,32) CP_COMMIT;
    ST_A(2,64) ST_B(2,64) CP_COMMIT;

    for (int kt=0; kt<KT; kt++){
        CP_WAIT2;
        __syncthreads();
        if (kt+3 < KT){ int st=(kt+3)&3; int K0=(kt+3)*32; ST_A(st,K0) ST_B(st,K0) }
        CP_COMMIT;
        const int buf = kt&3;
        __half* sAb = sA + buf*4096;
        unsigned* sBb = sBu + buf*2176;
#pragma unroll
        for (int ks=0;ks<2;ks++){
            unsigned af[4][4], bf[4][2];
            LOAD_AF16(af, sAb, wm, ks, lane)
#pragma unroll
            for (int j=0;j<4;j++){
                int c = wn*32 + j*8 + gid;
                bf[j][0]=sBb[(ks*8+tig  )*136 + c];
                bf[j][1]=sBb[(ks*8+tig+4)*136 + c];
            }
#pragma unroll
            for (int i=0;i<4;i++)
#pragma unroll
                for (int j=0;j<4;j++) mma_f16(acc[i][j], af[i], bf[j]);
        }
    }
#undef ST_A
#undef ST_B

#pragma unroll
    for (int i=0;i<4;i++){
        int row = m0 + wm*64 + i*16 + gid;
        float bv0 = bias[row], bv8 = bias[row+8];
        float* y0 = Y + (size_t)(b*C_ + row)*T_;
        float* y8 = Y + (size_t)(b*C_ + row+8)*T_;
#pragma unroll
        for (int j=0;j<4;j++){
            int col = n0 + wn*32 + j*8 + tig*2;
            *(float2*)(y0+col)=make_float2(acc[i][j][0]+bv0, acc[i][j][1]+bv0);
            *(float2*)(y8+col)=make_float2(acc[i][j][2]+bv8, acc[i][j][3]+bv8);
        }
    }
}

/* =========== fp16 fused Q/K/V ============ */
__launch_bounds__(256,2)
__global__ void g_qkv(const __half* __restrict__ X2h,
                      const __half* __restrict__ Wq, const __half* __restrict__ Wk, const __half* __restrict__ Wv,
                      const float* __restrict__ bq, const float* __restrict__ bk, const float* __restrict__ bv,
                      __half* __restrict__ Yq, __half* __restrict__ Yk, __half* __restrict__ Yv)
{
    extern __shared__ char smraw[];
    __half* sA = (__half*)smraw;
    __half2* sB2 = (__half2*)(smraw + 4*4096*2);
    unsigned* sBu = (unsigned*)sB2;
    const int n0 = blockIdx.x*128;
    const int mi = blockIdx.y;
    const int sel = mi >> 2;
    const int m0 = (mi & 3)*128;
    const int b  = blockIdx.z;
    const __half* Wm = (sel==0)?Wq:(sel==1)?Wk:Wv;
    const float* bias= (sel==0)?bq:(sel==1)?bk:bv;
    const float alpha= (sel==0)?0.125f:1.f;

    const int tid = threadIdx.x;
    const int lane = tid & 31, wid = tid >> 5;
    const int gid = lane >> 2, tig = lane & 3;
    const int wm = wid & 1, wn = wid >> 1;

    const __half2* X2 = (const __half2*)X2h + (size_t)b*256*T_;
    const int rowB = tid >> 4, colB = (tid & 15)*8;

    float acc[4][4][4];
#pragma unroll
    for (int i=0;i<4;i++)
#pragma unroll
        for (int j=0;j<4;j++)
#pragma unroll
            for (int u=0;u<4;u++) acc[i][j][u]=0.f;

    const int KT = C_/32;
#define ST_A(st,K0) { const __half* ap = Wm + (size_t)(m0>>7)*65536 + (size_t)((K0)>>5)*4096 + tid*16; \
                      __half* d = sA + (st)*4096 + tid*16; cp16(d,ap); cp16(d+8,ap+8); }
#define ST_B(st,K0) { const __half2* bp = X2 + (size_t)(((K0)>>1) + rowB)*T_ + n0 + colB; \
                      __half2* d = sB2 + (st)*2176 + rowB*136 + colB; cp16(d,bp); cp16(d+4,bp+4); }
    ST_A(0,0)  ST_B(0,0)  CP_COMMIT;
    ST_A(1,32) ST_B(1,32) CP_COMMIT;
    ST_A(2,64) ST_B(2,64) CP_COMMIT;

    for (int kt=0; kt<KT; kt++){
        CP_WAIT2;
        __syncthreads();
        if (kt+3 < KT){ int st=(kt+3)&3; int K0=(kt+3)*32; ST_A(st,K0) ST_B(st,K0) }
        CP_COMMIT;
        const int buf = kt&3;
        __half* sAb = sA + buf*4096;
        unsigned* sBb = sBu + buf*2176;
#pragma unroll
        for (int ks=0;ks<2;ks++){
            unsigned af[4][4], bf[4][2];
            LOAD_AF16(af, sAb, wm, ks, lane)
#pragma unroll
            for (int j=0;j<4;j++){
                int c = wn*32 + j*8 + gid;
                bf[j][0]=sBb[(ks*8+tig  )*136 + c];
                bf[j][1]=sBb[(ks*8+tig+4)*136 + c];
            }
#pragma unroll
            for (int i=0;i<4;i++)
#pragma unroll
                for (int j=0;j<4;j++) mma_f16(acc[i][j], af[i], bf[j]);
        }
    }
#undef ST_A
#undef ST_B

#pragma unroll
    for (int i=0;i<4;i++){
        int row = m0 + wm*64 + i*16 + gid;
        float bv0 = bias[row], bv8 = bias[row+8];
        int h0 = row>>6, dv = row&63;
        if (sel==0){
            __half* base = Yq + (size_t)(b*H_+h0)*T_*64;
#pragma unroll
            for (int j=0;j<4;j++){
                int col = n0 + wn*32 + j*8 + tig*2;
                base[(size_t)col*64 + dv]        = __float2half_rn(alpha*(acc[i][j][0]+bv0));
                base[(size_t)(col+1)*64 + dv]    = __float2half_rn(alpha*(acc[i][j][1]+bv0));
                base[(size_t)col*64 + dv+8]      = __float2half_rn(alpha*(acc[i][j][2]+bv8));
                base[(size_t)(col+1)*64 + dv+8]  = __float2half_rn(alpha*(acc[i][j][3]+bv8));
            }
        } else if (sel==1){
            __half* base = Yk + (size_t)(b*H_+h0)*32*T_*2;
#pragma unroll
            for (int j=0;j<4;j++){
                int col = n0 + wn*32 + j*8 + tig*2;
                base[(((size_t)(dv>>1))*T_ + col)*2 + (dv&1)]       = __float2half_rn(acc[i][j][0]+bv0);
                base[(((size_t)(dv>>1))*T_ + col+1)*2 + (dv&1)]     = __float2half_rn(acc[i][j][1]+bv0);
                base[(((size_t)((dv+8)>>1))*T_ + col)*2 + (dv&1)]   = __float2half_rn(acc[i][j][2]+bv8);
                base[(((size_t)((dv+8)>>1))*T_ + col+1)*2 + (dv&1)] = __float2half_rn(acc[i][j][3]+bv8);
            }
        } else {
            __half* base = Yv + (size_t)(b*H_+h0)*256*64*2;
#pragma unroll
            for (int j=0;j<4;j++){
                int col = n0 + wn*32 + j*8 + tig*2;
                base[(((size_t)(col>>1))*64 + dv)*2 + 0]   = __float2half_rn(acc[i][j][0]+bv0);
                base[(((size_t)(col>>1))*64 + dv)*2 + 1]   = __float2half_rn(acc[i][j][1]+bv0);
                base[(((size_t)(col>>1))*64 + dv+8)*2 + 0] = __float2half_rn(acc[i][j][2]+bv8);
                base[(((size_t)(col>>1))*64 + dv+8)*2 + 1] = __float2half_rn(acc[i][j][3]+bv8);
            }
        }
    }
}

/* =========== fp16 scores: P = Qh @ Kh, out fp32 ============ */
__launch_bounds__(256,2)
__global__ void g_sc(const __half* __restrict__ Qh, const __half* __restrict__ Kh,
                     float* __restrict__ P)
{
    extern __shared__ char smraw[];
    __half* sA = (__half*)smraw;
    unsigned* sBu = (unsigned*)(smraw + 4*5120*2);
    const int s0 = blockIdx.x*128;
    const int t0 = blockIdx.y*128;
    const int bh = blockIdx.z;
    const int tid = threadIdx.x;
    const int lane = tid & 31, wid = tid >> 5;
    const int gid = lane >> 2, tig = lane & 3;
    const int wm = wid & 1, wn = wid >> 1;

    const __half* qb = Qh + (size_t)bh*T_*64;
    const __half2* kb = (const __half2*)Kh + (size_t)bh*32*T_;
    const int rowA = tid >> 1, colA = (tid & 1)*16;
    const int rowB = tid >> 4, colB = (tid & 15)*8;

    float acc[4][4][4];
#pragma unroll
    for (int i=0;i<4;i++)
#pragma unroll
        for (int j=0;j<4;j++)
#pragma unroll
            for (int u=0;u<4;u++) acc[i][j][u]=0.f;

#define ST_A(st,K0) { const __half* ap = qb + (size_t)(t0+rowA)*64 + (K0) + colA; \
                      __half* d = sA + (st)*5120 + rowA*40 + colA; cp16(d,ap); cp16(d+8,ap+8); }
#define ST_B(st,K0) { const __half2* bp = kb + (size_t)(((K0)>>1)+rowB)*T_ + s0 + colB; \
                      __half2* d = (__half2*)sBu + (size_t)(st)*2176 + rowB*136 + colB; \
                      cp16(d,bp); cp16(d+4,bp+4); }
    ST_A(0,0)  ST_B(0,0)  CP_COMMIT;
    ST_A(1,32) ST_B(1,32) CP_COMMIT;
    CP_COMMIT;

    for (int kt=0; kt<2; kt++){
        CP_WAIT2;
        __syncthreads();
        CP_COMMIT;
        const int buf = kt;
        __half* sAb = sA + buf*5120;
        unsigned* sBb = sBu + buf*2176;
#pragma unroll
        for (int ks=0;ks<2;ks++){
            unsigned af[4][4], bf[4][2];
#pragma unroll
            for (int i=0;i<4;i++){
                int r = wm*64 + i*16 + gid;
                af[i][0]=*(const unsigned*)(sAb + (size_t)r*40 + ks*16 + tig*2);
                af[i][1]=*(const unsigned*)(sAb + (size_t)(r+8)*40 + ks*16 + tig*2);
                af[i][2]=*(const unsigned*)(sAb + (size_t)r*40 + ks*16 + tig*2 + 8);
                af[i][3]=*(const unsigned*)(sAb + (size_t)(r+8)*40 + ks*16 + tig*2 + 8);
            }
#pragma unroll
            for (int j=0;j<4;j++){
                int c = wn*32 + j*8 + gid;
                bf[j][0]=sBb[(ks*8+tig  )*136 + c];
                bf[j][1]=sBb[(ks*8+tig+4)*136 + c];
            }
#pragma unroll
            for (int i=0;i<4;i++)
#pragma unroll
                for (int j=0;j<4;j++) mma_f16(acc[i][j], af[i], bf[j]);
        }
    }
#undef ST_A
#undef ST_B

#pragma unroll
    for (int i=0;i<4;i++){
        int row = t0 + wm*64 + i*16 + gid;
        float* y0 = P + ((size_t)bh*T_ + row)*T_;
        float* y8 = P + ((size_t)bh*T_ + row+8)*T_;
#pragma unroll
        for (int j=0;j<4;j++){
            int col = s0 + wn*32 + j*8 + tig*2;
            *(float2*)(y0+col)=make_float2(acc[i][j][0], acc[i][j][1]);
            *(float2*)(y8+col)=make_float2(acc[i][j][2], acc[i][j][3]);
        }
    }
}

/* =========== fp16 ctx: Ph @ Vh + rel-V band -> hC packed fp16 ============ */
__launch_bounds__(256,2)
__global__ void g_ctx(const __half* __restrict__ Ph, const __half* __restrict__ Vh,
                      const float* __restrict__ erv, __half* __restrict__ Ch)
{
    extern __shared__ char smraw[];
    __half* sA = (__half*)smraw;
    unsigned* sBu = (unsigned*)(smraw + 4*5120*2);
    float* sErv = (float*)(smraw + 4*5120*2 + 4*1152*4);
    const int t0 = blockIdx.x*128;
    const int bh = blockIdx.y;
    const int b  = bh >> 3, h = bh & 7;
    const int tid = threadIdx.x;
    const int lane = tid & 31, wid = tid >> 5;
    const int gid = lane >> 2, tig = lane & 3;
    const int wm = wid & 1, wn = wid >> 1;

    const __half* pb = Ph + (size_t)bh*T_*T_;
    const __half2* vb = (const __half2*)Vh + (size_t)bh*256*64;
    const int rowA = tid >> 1, colA = (tid & 1)*16;
    const int rowB = tid >> 4, colB = (tid & 15)*4;

    for (int l=tid; l<21*64; l+=256) sErv[l]=erv[l];

    float acc[4][2][4];
#pragma unroll
    for (int i=0;i<4;i++)
#pragma unroll
        for (int j=0;j<2;j++)
#pragma unroll
            for (int u=0;u<4;u++) acc[i][j][u]=0.f;

#define ST_A(st,K0) { const __half* ap = pb + (size_t)(t0+rowA)*T_ + (K0) + colA; \
                      __half* d = sA + (st)*5120 + rowA*40 + colA; cp16(d,ap); cp16(d+8,ap+8); }
#define ST_B(st,K0) { const __half2* bp = vb + (size_t)(((K0)>>1)+rowB)*64 + colB; \
                      __half2* d = (__half2*)sBu + (size_t)(st)*1152 + rowB*72 + colB; cp16(d,bp); }
    ST_A(0,0)  ST_B(0,0)  CP_COMMIT;
    ST_A(1,32) ST_B(1,32) CP_COMMIT;
    ST_A(2,64) ST_B(2,64) CP_COMMIT;

    const int KT = T_/32;
    for (int kt=0; kt<KT; kt++){
        CP_WAIT2;
        __syncthreads();
        if (kt+3 < KT){ int st=(kt+3)&3; int K0=(kt+3)*32; ST_A(st,K0) ST_B(st,K0) }
        CP_COMMIT;
        const int buf = kt&3;
        __half* sAb = sA + buf*5120;
        unsigned* sBb = sBu + buf*1152;
#pragma unroll
        for (int ks=0;ks<2;ks++){
            unsigned af[4][4], bf[2][2];
#pragma unroll
            for (int i=0;i<4;i++){
                int r = wm*64 + i*16 + gid;
                af[i][0]=*(const unsigned*)(sAb + (size_t)r*40 + ks*16 + tig*2);
                af[i][1]=*(const unsigned*)(sAb + (size_t)(r+8)*40 + ks*16 + tig*2);
                af[i][2]=*(const unsigned*)(sAb + (size_t)r*40 + ks*16 + tig*2 + 8);
                af[i][3]=*(const unsigned*)(sAb + (size_t)(r+8)*40 + ks*16 + tig*2 + 8);
            }
#pragma unroll
            for (int j=0;j<2;j++){
                int c = wn*16 + j*8 + gid;
                bf[j][0]=sBb[(ks*8+tig  )*72 + c];
                bf[j][1]=sBb[(ks*8+tig+4)*72 + c];
            }
#pragma unroll
            for (int i=0;i<4;i++)
#pragma unroll
                for (int j=0;j<2;j++) mma_f16(acc[i][j], af[i], bf[j]);
        }
    }
#undef ST_A
#undef ST_B

#pragma unroll
    for (int i=0;i<4;i++){
#pragma unroll
        for (int rr=0; rr<2; rr++){
            int t = t0 + wm*64 + i*16 + gid + rr*8;
            const __half* prow = pb + (size_t)t*T_;
            for (int r=0;r<21;r++){
                int s = t + r - WIN_;
                if ((unsigned)s < (unsigned)T_){
                    float pv = __half2float(prow[s]);
#pragma unroll
                    for (int j=0;j<2;j++){
                        int d = wn*16 + j*8 + tig*2;
                        acc[i][j][rr*2+0] += pv*sErv[r*64 + d];
                        acc[i][j][rr*2+1] += pv*sErv[r*64 + d+1];
                    }
                }
            }
        }
    }

    __half2* C2 = (__half2*)Ch;
#pragma unroll
    for (int i=0;i<4;i++){
        int row = t0 + wm*64 + i*16 + gid;
#pragma unroll
        for (int j=0;j<2;j++){
            int c = h*64 + wn*16 + j*8 + tig*2;
            __half2* cp = C2 + (size_t)(b*256 + (c>>1))*T_;
            cp[row]   = __floats2half2_rn(acc[i][j][0], acc[i][j][1]);
            cp[row+8] = __floats2half2_rn(acc[i][j][2], acc[i][j][3]);
        }
    }
}

/* =========== fp16 K=3 conv as 3 tap-GEMMs =========== */
__launch_bounds__(256,2)
__global__ void gconv3p(const __half* __restrict__ Xp, const __half* __restrict__ Wc,
                        const float* __restrict__ bias, const float* __restrict__ mask,
                        float* __restrict__ Y, __half* __restrict__ Yh,
                        int Cin, int Cout, int mode, int ktiles)
{
    extern __shared__ char smraw[];
    __half* sA = (__half*)smraw;
    __half* sX = (__half*)(smraw + 4*6144*2);
    const int n0 = blockIdx.x*128;
    const int m0 = blockIdx.y*128;
    const int bz = blockIdx.z;
    const int b    = (mode==1) ? (bz & 7) : bz;
    const int part = (mode==1) ? (bz >> 3) : 0;
    const int kOff16 = part*ktiles;

    const int tid = threadIdx.x;
    const int lane = tid & 31, wid = tid >> 5;
    const int gid = lane >> 2, tig = lane & 3;
    const int wm = wid & 1, wn = wid >> 1;

    const __half* xb = Xp + (size_t)b*516*Cin;
    const size_t wmt = (size_t)(m0>>7)*((size_t)Cin*384);

    float acc[4][4][4];
#pragma unroll
    for (int i=0;i<4;i++)
#pragma unroll
        for (int j=0;j<4;j++)
#pragma unroll
            for (int u=0;u<4;u++) acc[i][j][u]=0.f;

#define ST_A(st,ct) { const __half* ap = Wc + wmt + (size_t)(ct)*6144 + tid*24; \
                      __half* d = sA + (st)*6144 + tid*24; \
                      cp16(d,ap); cp16(d+8,ap+8); cp16(d+16,ap+16); }
#define ST_B(st,ct) { int c0 = (ct)*16; \
                      { int r = tid>>1, q = tid&1; \
                        const __half* bp = xb + (size_t)(n0 + r)*Cin + c0 + q*8; \
                        cp16(sX + (st)*3120 + r*24 + q*8, bp); } \
                      { int slot = tid+256; if (slot < 260){ int r = slot>>1, q = slot&1; \
                        const __half* bp = xb + (size_t)(n0 + r)*Cin + c0 + q*8; \
                        cp16(sX + (st)*3120 + r*24 + q*8, bp); } } }
    if (0 < ktiles){ ST_A(0,kOff16)   ST_B(0,kOff16)   } CP_COMMIT;
    if (1 < ktiles){ ST_A(1,kOff16+1) ST_B(1,kOff16+1) } CP_COMMIT;
    if (2 < ktiles){ ST_A(2,kOff16+2) ST_B(2,kOff16+2) } CP_COMMIT;

    for (int kt=0; kt<ktiles; kt++){
        CP_WAIT2;
        __syncthreads();
        if (kt+3 < ktiles){ int st=(kt+3)&3; int ct=kOff16+kt+3; ST_A(st,ct) ST_B(st,ct) }
        CP_COMMIT;
        const int buf = kt&3;
        const __half* sAb = sA + buf*6144;
        const unsigned* sXu = (const unsigned*)(sX + buf*3120);
#pragma unroll
        for (int tap=0; tap<3; tap++){
            unsigned af[4][4], bf[4][2];
#pragma unroll
            for (int i=0;i<4;i++){
                const float4 av = *(const float4*)(sAb + tap*2048 + ((wm*4+i)*32 + lane)*8);
                af[i][0]=__float_as_uint(av.x); af[i][1]=__float_as_uint(av.y);
                af[i][2]=__float_as_uint(av.z); af[i][3]=__float_as_uint(av.w);
            }
#pragma unroll
            for (int j=0;j<4;j++){
                int rrow = wn*32 + j*8 + gid + tap;
                bf[j][0]=sXu[rrow*12 + tig    ];
                bf[j][1]=sXu[rrow*12 + tig + 4];
            }
#pragma unroll
            for (int i=0;i<4;i++)
#pragma unroll
                for (int j=0;j<4;j++) mma_f16(acc[i][j], af[i], bf[j]);
        }
    }
#undef ST_A
#undef ST_B

    if (mode==0){
        const float* mb = mask + b*T_;
#pragma unroll
        for (int i=0;i<4;i++){
            int row = m0 + wm*64 + i*16 + gid;
            float bv0 = bias[row], bv8 = bias[row+8];
#pragma unroll
            for (int j=0;j<4;j++){
                int col = n0 + wn*32 + j*8 + tig*2;
                float m0v = mb[col], m1v = mb[col+1];
                __half* p0 = Yh + (size_t)(b*516 + col+1)*F_;
                __half* p1 = Yh + (size_t)(b*516 + col+2)*F_;
                p0[row]   = __float2half_rn(fmaxf(acc[i][j][0]+bv0, 0.f)*m0v);
                p1[row]   = __float2half_rn(fmaxf(acc[i][j][1]+bv0, 0.f)*m1v);
                p0[row+8] = __float2half_rn(fmaxf(acc[i][j][2]+bv8, 0.f)*m0v);
                p1[row+8] = __float2half_rn(fmaxf(acc[i][j][3]+bv8, 0.f)*m1v);
            }
        }
    } else {
#pragma unroll
        for (int i=0;i<4;i++){
            int row = m0 + wm*64 + i*16 + gid;
            float* y0 = Y + (size_t)part*ELT_X + (size_t)(b*Cout + row)*T_;
            float* y8 = Y + (size_t)part*ELT_X + (size_t)(b*Cout + row+8)*T_;
#pragma unroll
            for (int j=0;j<4;j++){
                int col = n0 + wn*32 + j*8 + tig*2;
                *(float2*)(y0+col)=make_float2(acc[i][j][0], acc[i][j][1]);
                *(float2*)(y8+col)=make_float2(acc[i][j][2], acc[i][j][3]);
            }
        }
    }
}

/* ---- fused softmax: parallel band(q·erk) + mask + softmax; fp32 in, fp16 out ---- */
__launch_bounds__(256)
__global__ void k_softmax(const float* __restrict__ P, const float* __restrict__ mask,
                          const __half* __restrict__ Qh, const float* __restrict__ erk,
                          __half* __restrict__ Ph)
{
    const int row = blockIdx.x;
    const int t  = row & (T_-1);
    const int bh = row >> 9;
    const int b  = bh >> 3;
    const float* p = P + (size_t)row*T_;
    __half* ph = Ph + (size_t)row*T_;
    const float* mb = mask + b*T_;
    const int tid = threadIdx.x;
    const int lane = tid & 31, w = tid >> 5;

    __shared__ float band[24];
    {
        const __half* qr = Qh + ((size_t)bh*T_ + t)*64;
        float q0 = __half2float(qr[lane]);
        float q1 = __half2float(qr[32+lane]);
        for (int r = w; r < 21; r += 8){
            float s = q0*erk[r*64+lane] + q1*erk[r*64+32+lane];
#pragma unroll
            for (int o=16;o;o>>=1) s += __shfl_xor_sync(0xffffffffu, s, o);
            if (lane==0) band[r] = s;
        }
    }
    __syncthreads();

    const float mt = mb[t];
    int r0 = tid - t + WIN_;
    int r1 = tid + 256 - t + WIN_;
    float p0 = p[tid]     + (((unsigned)r0 < 21u) ? band[r0] : 0.f);
    float p1 = p[tid+256] + (((unsigned)r1 < 21u) ? band[r1] : 0.f);
    float v0 = (mt*mb[tid]     != 0.f) ? p0 : -1e4f;
    float v1 = (mt*mb[tid+256] != 0.f) ? p1 : -1e4f;
    __shared__ float red[8];
    float m = fmaxf(v0,v1);
#pragma unroll
    for (int o=16;o;o>>=1) m = fmaxf(m, __shfl_xor_sync(0xffffffffu, m, o));
    if (lane==0) red[w]=m;
    __syncthreads();
    float mx = red[0];
#pragma unroll
    for (int k2=1;k2<8;k2++) mx = fmaxf(mx, red[k2]);
    float e0 = expf(v0-mx), e1 = expf(v1-mx);
    float s = e0+e1;
#pragma unroll
    for (int o=16;o;o>>=1) s += __shfl_xor_sync(0xffffffffu, s, o);
    __syncthreads();
    if (lane==0) red[w]=s;
    __syncthreads();
    float tot = 0.f;
#pragma unroll
    for (int k2=0;k2<8;k2++) tot += red[k2];
    float inv = 1.f/tot;
    ph[tid]     = __float2half_rn(e0*inv);
    ph[tid+256] = __float2half_rn(e1*inv);
}

/* ---- residual add + LN (after attention); emits padded fp16 x ---- */
__launch_bounds__(512)
__global__ void k_addln(float* __restrict__ X, const float* __restrict__ Yv,
                        const float* __restrict__ gamma, const float* __restrict__ beta,
                        __half* __restrict__ Xp, const float* __restrict__ mask)
{
    const int b = blockIdx.y;
    const int tl = threadIdx.x & 31;
    const int slot = threadIdx.x >> 5;
    const int t = blockIdx.x*32 + tl;
    __shared__ float ssum[16][33];
    __shared__ float ssq[16][33];
    float vals[32];
    float s=0.f, q=0.f;
    size_t base = (size_t)b*C_*T_ + t;
#pragma unroll
    for (int u=0;u<32;u++){
        int c = slot*32+u;
        float v = X[base + (size_t)c*T_] + Yv[base + (size_t)c*T_];
        vals[u]=v; s+=v; q+=v*v;
    }
    ssum[slot][tl]=s; ssq[slot][tl]=q;
    __syncthreads();
    float m=0.f, vv=0.f;
#pragma unroll
    for (int k2=0;k2<16;k2++){ m+=ssum[k2][tl]; vv+=ssq[k2][tl]; }
    m *= (1.f/512.f);
    vv = vv*(1.f/512.f) - m*m;
    float r = rsqrtf(vv + 1e-5f);
    float mk = mask[b*T_ + t];
#pragma unroll
    for (int u=0;u<32;u++){
        int c = slot*32+u;
        float o = (vals[u]-m)*r*gamma[c] + beta[c];
        X[base + (size_t)c*T_] = o;
        Xp[(size_t)(b*516 + t+1)*C_ + c] = __float2half_rn(o*mk);
    }
}

/* ---- fused: conv split-K reduce + bias + mask + residual + LN; emits packed-pair fp16 */
__launch_bounds__(512)
__global__ void k_addln2(float* __restrict__ X, const float* __restrict__ P0,
                         const float* __restrict__ bias2,
                         const float* __restrict__ gamma, const float* __restrict__ beta,
                         __half* __restrict__ Xr, const float* __restrict__ mask)
{
    const int b = blockIdx.y;
    const int tl = threadIdx.x & 31;
    const int slot = threadIdx.x >> 5;
    const int t = blockIdx.x*32 + tl;
    __shared__ float ssum[16][33];
    __shared__ float ssq[16][33];
    float vals[32];
    float s=0.f, q=0.f;
    size_t base = (size_t)b*C_*T_ + t;
    const float mk = mask[b*T_ + t];
#pragma unroll
    for (int u=0;u<32;u++){
        int c = slot*32+u;
        size_t idx = base + (size_t)c*T_;
        float y = (P0[idx] + P0[(size_t)ELT_X + idx] + bias2[c]) * mk;
        float v = X[idx] + y;
        vals[u]=v; s+=v; q+=v*v;
    }
    ssum[slot][tl]=s; ssq[slot][tl]=q;
    __syncthreads();
    float m=0.f, vv=0.f;
#pragma unroll
    for (int k2=0;k2<16;k2++){ m+=ssum[k2][tl]; vv+=ssq[k2][tl]; }
    m *= (1.f/512.f);
    vv = vv*(1.f/512.f) - m*m;
    float r = rsqrtf(vv + 1e-5f);
#pragma unroll
    for (int u=0;u<32;u++){
        int c = slot*32+u;
        float o = (vals[u]-m)*r*gamma[c] + beta[c];
        X[base + (size_t)c*T_] = o;
        Xr[((size_t)(b*256 + (c>>1))*T_ + t)*2 + (c&1)] = __float2half_rn(o);
    }
}

/* ---------------- host orchestration ---------------- */
extern "C" void kernel_launch(void* const* d_in, const int* in_sizes, int n_in,
                              void* d_out, int out_size)
{
    (void)in_sizes; (void)n_in; (void)out_size;
    const float* x_in = (const float*)d_in[0];
    const float* mask = (const float*)d_in[1];
    const float* Wq  = (const float*)d_in[2];
    const float* bq  = (const float*)d_in[3];
    const float* Wk  = (const float*)d_in[4];
    const float* bk  = (const float*)d_in[5];
    const float* Wv  = (const float*)d_in[6];
    const float* bv  = (const float*)d_in[7];
    const float* Wo  = (const float*)d_in[8];
    const float* bo  = (const float*)d_in[9];
    const float* erk = (const float*)d_in[10];
    const float* erv = (const float*)d_in[11];
    const float* g1  = (const float*)d_in[12];
    const float* b1  = (const float*)d_in[13];
    const float* g2  = (const float*)d_in[14];
    const float* b2  = (const float*)d_in[15];
    const float* W1  = (const float*)d_in[16];
    const float* bf1 = (const float*)d_in[17];
    const float* W2  = (const float*)d_in[18];
    const float* bf2 = (const float*)d_in[19];

    const int SM_GW  = 4*(4096 + 2176*2)*2;
    const int SM_SC  = 4*5120*2 + 4*2176*4;
    const int SM_CTX = 4*5120*2 + 4*1152*4 + 21*64*4;
    const int SM_CV  = 4*(6144 + 3120)*2;
    cudaFuncSetAttribute(g1x1,   cudaFuncAttributeMaxDynamicSharedMemorySize, SM_GW);
    cudaFuncSetAttribute(g_qkv,  cudaFuncAttributeMaxDynamicSharedMemorySize, SM_GW);
    cudaFuncSetAttribute(g_sc,   cudaFuncAttributeMaxDynamicSharedMemorySize, SM_SC);
    cudaFuncSetAttribute(g_ctx,  cudaFuncAttributeMaxDynamicSharedMemorySize, SM_CTX);
    cudaFuncSetAttribute(gconv3p,cudaFuncAttributeMaxDynamicSharedMemorySize, SM_CV);

    float* pool = 0;
    cudaGetSymbolAddress((void**)&pool, g_pool);
    float* px = pool;
    float* pq = pool + (size_t)1*ELT_X;   /* conv split-K partials (slots 1,2) */
    float* py = pool + (size_t)3*ELT_X;   /* Wo output */
    float* pp = pool + (size_t)4*ELT_X;   /* scores fp32 (ELT_P) */
    __half* hb  = (__half*)(pool + (size_t)4*ELT_X + ELT_P + ELT_X);
    __half* hXr  = hb;
    __half* hC   = hXr + (size_t)ELT_X;
    __half* hXp1 = hC  + (size_t)ELT_X;
    __half* hXp2 = hXp1 + (size_t)B_*516*C_;
    __half* hWq  = hXp2 + (size_t)B_*516*F_;
    __half* hWk  = hWq + WQKV;
    __half* hWv  = hWk + WQKV;
    __half* hWo  = hWv + WQKV;
    __half* hW1  = hWo + WQKV;
    __half* hW2  = hW1 + WFF;
    __half* hQ   = hW2 + WFF;
    __half* hK   = hQ + (size_t)ELT_X;
    __half* hV   = hK + (size_t)ELT_X;
    __half* hP   = hV + (size_t)ELT_X;

    size_t mszQ = (size_t)C_*C_;
    k_swizA16<<<(unsigned)((WQKV+255)/256),256>>>(Wq, hWq, C_, mszQ, WQKV);
    k_swizA16<<<(unsigned)((WQKV+255)/256),256>>>(Wk, hWk, C_, mszQ, WQKV);
    k_swizA16<<<(unsigned)((WQKV+255)/256),256>>>(Wv, hWv, C_, mszQ, WQKV);
    k_swizA16<<<(unsigned)((WQKV+255)/256),256>>>(Wo, hWo, C_, mszQ, WQKV);
    k_swizC16<<<(unsigned)((WFF+255)/256),256>>>(W1, hW1, C_, (size_t)F_*C_*3, WFF);
    k_swizC16<<<(unsigned)((WFF+255)/256),256>>>(W2, hW2, F_, (size_t)C_*F_*3, WFF);

    k_maskmul2<<<ELT_X/256,256>>>(x_in, mask, px, hXr);
    k_zb16<<<20480/256,256>>>(hXp1, hXp2);

    for (int L=0;L<6;L++){
        g_qkv<<<dim3(T_/128, 12, B_),256,SM_GW>>>(hXr, hWq + L*mszQ, hWk + L*mszQ, hWv + L*mszQ,
                                                  bq+L*C_, bk+L*C_, bv+L*C_, hQ, hK, hV);
        g_sc<<<dim3(T_/128, T_/128, B_*H_),256,SM_SC>>>(hQ, hK, pp);
        k_softmax<<<B_*H_*T_,256>>>(pp, mask, hQ, erk + L*21*64, hP);
        g_ctx<<<dim3(T_/128, B_*H_),256,SM_CTX>>>(hP, hV, erv + L*21*64, hC);
        g1x1<<<dim3(T_/128, C_/128, B_),256,SM_GW>>>(hWo + L*mszQ, hC, bo + L*C_, py);
        k_addln<<<dim3(T_/32,B_),512>>>(px, py, g1+L*C_, b1+L*C_, hXp1, mask);

        gconv3p<<<dim3(T_/128, F_/128, B_),256,SM_CV>>>(hXp1, hW1 + (size_t)L*F_*C_*3,
                                                        bf1+L*F_, mask, (float*)0, hXp2,
                                                        C_, F_, 0, C_/16);
        gconv3p<<<dim3(T_/128, C_/128, 2*B_),256,SM_CV>>>(hXp2, hW2 + (size_t)L*C_*F_*3,
                                                          bf2+L*C_, mask, pq, (__half*)0,
                                                          F_, C_, 1, F_/32);
        k_addln2<<<dim3(T_/32,B_),512>>>(px, pq, bf2+L*C_, g2+L*C_, b2+L*C_, hXr, mask);
    }
    k_maskmul<<<ELT_X/256,256>>>(px, mask, (float*)d_out);
}

// round 17
// speedup vs baseline: 1.0782x; 1.0609x over previous
#include <cuda_runtime.h>
#include <cuda_fp16.h>
#include <math.h>

#define B_ 8
#define T_ 512
#define C_ 512
#define H_ 8
#define F_ 2048
#define WIN_ 10

#define ELT_X (B_*C_*T_)
#define ELT_P (B_*H_*T_*T_)
#define WQKV ((size_t)6*C_*C_)
#define WFF  ((size_t)6*F_*C_*3)

#define HALFS ((size_t)5*ELT_X + (size_t)B_*516*(C_+F_) + 4*WQKV + 2*WFF + ELT_P)
__device__ float g_pool[(size_t)5*ELT_X + ELT_P + (HALFS+1)/2];

__device__ __forceinline__ void mma_f16(float c[4], const unsigned a[4], const unsigned b[2]){
    asm("mma.sync.aligned.m16n8k16.row.col.f32.f16.f16.f32 "
        "{%0,%1,%2,%3}, {%4,%5,%6,%7}, {%8,%9}, {%0,%1,%2,%3};"
        : "+f"(c[0]), "+f"(c[1]), "+f"(c[2]), "+f"(c[3])
        : "r"(a[0]), "r"(a[1]), "r"(a[2]), "r"(a[3]), "r"(b[0]), "r"(b[1]));
}
__device__ __forceinline__ void cp16(void* smem, const void* g){
    unsigned s = (unsigned)__cvta_generic_to_shared(smem);
    asm volatile("cp.async.ca.shared.global [%0], [%1], 16;" :: "r"(s), "l"(g));
}
#define CP_COMMIT asm volatile("cp.async.commit_group;" ::: "memory")
#define CP_WAIT2  asm volatile("cp.async.wait_group 2;" ::: "memory")

/* ===== combined, vectorized fp16 weight swizzle: 1 fragment row (8 halfs)/thread ===== */
__global__ void k_swizAll(const float* __restrict__ Wq, const float* __restrict__ Wk,
                          const float* __restrict__ Wv, const float* __restrict__ Wo,
                          const float* __restrict__ W1, const float* __restrict__ W2,
                          __half* __restrict__ hWq, __half* __restrict__ hWk,
                          __half* __restrict__ hWv, __half* __restrict__ hWo,
                          __half* __restrict__ hW1, __half* __restrict__ hW2)
{
    const size_t D8 = WQKV/8;   /* 196,608  */
    const size_t C8 = WFF/8;    /* 2,359,296 */
    size_t t8 = (size_t)blockIdx.x*256 + threadIdx.x;
    __half out[8];
    __half* dst;

    if (t8 < 4*D8){
        int w = (int)(t8 / D8);
        size_t od8 = t8 - (size_t)w*D8;
        const float* S = (w==0)?Wq:(w==1)?Wk:(w==2)?Wv:Wo;
        dst = ((w==0)?hWq:(w==1)?hWk:(w==2)?hWv:hWo) + od8*8;
        size_t l = od8 >> 15;                 /* / (C*C/8) */
        int od = ((int)(od8 & 32767)) << 3;
        int gid = (od>>5)&7, tig = (od>>3)&3;
        int m0 = (od>>16)*128 + ((od>>9)&7)*16 + gid;
        int k0 = ((od>>12)&15)*32 + ((od>>8)&1)*16 + tig*2;
        const float* src = S + l*((size_t)C_*C_) + (size_t)m0*C_ + k0;
        float2 a0 = *(const float2*)(src);
        float2 a1 = *(const float2*)(src + 8);
        float2 b0 = *(const float2*)(src + 8*C_);
        float2 b1 = *(const float2*)(src + 8*C_ + 8);
        out[0]=__float2half_rn(a0.x); out[1]=__float2half_rn(a0.y);
        out[2]=__float2half_rn(b0.x); out[3]=__float2half_rn(b0.y);
        out[4]=__float2half_rn(a1.x); out[5]=__float2half_rn(a1.y);
        out[6]=__float2half_rn(b1.x); out[7]=__float2half_rn(b1.y);
    } else {
        size_t r = t8 - 4*D8;
        int isW1 = (r < C8);
        size_t od8 = isW1 ? r : (r - C8);
        const float* S = isW1 ? W1 : W2;
        dst = (isW1 ? hW1 : hW2) + od8*8;
        size_t l = od8 / 393216u;              /* per-layer 8-groups (= F*C*3/8) */
        int od = ((int)(od8 - l*393216u)) << 3;
        int mtile, rem;
        if (isW1){ mtile = od / (512*384);  rem = od - mtile*(512*384);  }
        else     { mtile = od / (2048*384); rem = od - mtile*(2048*384); }
        int ctile = rem / 6144;
        int rem2 = rem - ctile*6144;
        int tap  = rem2 >> 11;
        int mgrp = (rem2>>8)&7;
        int gid  = (rem2>>5)&7, tig = (rem2>>3)&3;
        int m0 = mtile*128 + mgrp*16 + gid;
        int c0 = ctile*16 + tig*2;
        size_t s3 = (size_t)(isW1 ? 512 : 2048)*3;
        const float* r0p = S + l*((size_t)F_*C_*3) + (size_t)m0*s3 + (size_t)c0*3 + tap;
        const float* r8p = r0p + 8*s3;
        out[0]=__float2half_rn(r0p[0]);  out[1]=__float2half_rn(r0p[3]);
        out[2]=__float2half_rn(r8p[0]);  out[3]=__float2half_rn(r8p[3]);
        out[4]=__float2half_rn(r0p[24]); out[5]=__float2half_rn(r0p[27]);
        out[6]=__float2half_rn(r8p[24]); out[7]=__float2half_rn(r8p[27]);
    }
    *(uint4*)dst = *(const uint4*)out;
}

/* ---- mask: px fp32 + hXr packed-pair fp16 ---- */
__global__ void k_maskmul2(const float* __restrict__ X, const float* __restrict__ mask,
                           float* __restrict__ Y, __half* __restrict__ Xr)
{
    int i = blockIdx.x*256 + threadIdx.x;
    int t = i & (T_-1);
    int c = (i >> 9) & (C_-1);
    int b = i >> 18;
    float v = X[i] * mask[b*T_ + t];
    Y[i] = v;
    Xr[((size_t)(b*256 + (c>>1))*T_ + t)*2 + (c&1)] = __float2half_rn(v);
}

/* ---- zero border rows of hXp1 / hXp2 ---- */
__global__ void k_zb16(__half* __restrict__ Xp1, __half* __restrict__ Xp2)
{
    int idx2 = blockIdx.x*256 + threadIdx.x;
    if (idx2 < 4096){
        int b = idx2 >> 9, rr = (idx2 >> 8) & 1, off = idx2 & 255;
        ((__half2*)Xp1)[((size_t)(b*516 + rr*513)*C_)/2 + off] = __half2half2(__float2half(0.f));
    } else {
        int j = idx2 - 4096;
        int b = j >> 11, rr = (j >> 10) & 1, off = j & 1023;
        ((__half2*)Xp2)[((size_t)(b*516 + rr*513)*F_)/2 + off] = __half2half2(__float2half(0.f));
    }
}

#define LOAD_AF16(af, sAh, wm, ks1, lane) \
    _Pragma("unroll") \
    for (int i=0;i<4;i++){ \
        const float4 av = *(const float4*)((sAh) + ((((wm)*4+i)*2+(ks1))*32 + (lane))*8); \
        af[i][0]=__float_as_uint(av.x); af[i][1]=__float_as_uint(av.y); \
        af[i][2]=__float_as_uint(av.z); af[i][3]=__float_as_uint(av.w); \
    }

/* =========== fp16 1x1 GEMM (Wo), full-K, bias in epilogue ============ */
__launch_bounds__(256,2)
__global__ void g1x1(const __half* __restrict__ Wm, const __half* __restrict__ X2h,
                     const float* __restrict__ bias, float* __restrict__ Y)
{
    extern __shared__ char smraw[];
    __half* sA = (__half*)smraw;
    __half2* sB2 = (__half2*)(smraw + 4*4096*2);
    unsigned* sBu = (unsigned*)sB2;
    const int n0 = blockIdx.x*128;
    const int m0 = blockIdx.y*128;
    const int b  = blockIdx.z;
    const int tid = threadIdx.x;
    const int lane = tid & 31, wid = tid >> 5;
    const int gid = lane >> 2, tig = lane & 3;
    const int wm = wid & 1, wn = wid >> 1;

    const __half2* X2 = (const __half2*)X2h + (size_t)b*256*T_;
    const int rowB = tid >> 4, colB = (tid & 15)*8;

    float acc[4][4][4];
#pragma unroll
    for (int i=0;i<4;i++)
#pragma unroll
        for (int j=0;j<4;j++)
#pragma unroll
            for (int u=0;u<4;u++) acc[i][j][u]=0.f;

    const int KT = C_/32;
#define ST_A(st,K0) { const __half* ap = Wm + (size_t)(m0>>7)*65536 + (size_t)((K0)>>5)*4096 + tid*16; \
                      __half* d = sA + (st)*4096 + tid*16; cp16(d,ap); cp16(d+8,ap+8); }
#define ST_B(st,K0) { const __half2* bp = X2 + (size_t)(((K0)>>1) + rowB)*T_ + n0 + colB; \
                      __half2* d = sB2 + (st)*2176 + rowB*136 + colB; cp16(d,bp); cp16(d+4,bp+4); }
    ST_A(0,0)  ST_B(0,0)  CP_COMMIT;
    ST_A(1,32) ST_B(1,32) CP_COMMIT;
    ST_A(2,64) ST_B(2,64) CP_COMMIT;

    for (int kt=0; kt<KT; kt++){
        CP_WAIT2;
        __syncthreads();
        if (kt+3 < KT){ int st=(kt+3)&3; int K0=(kt+3)*32; ST_A(st,K0) ST_B(st,K0) }
        CP_COMMIT;
        const int buf = kt&3;
        __half* sAb = sA + buf*4096;
        unsigned* sBb = sBu + buf*2176;
#pragma unroll
        for (int ks=0;ks<2;ks++){
            unsigned af[4][4], bf[4][2];
            LOAD_AF16(af, sAb, wm, ks, lane)
#pragma unroll
            for (int j=0;j<4;j++){
                int c = wn*32 + j*8 + gid;
                bf[j][0]=sBb[(ks*8+tig  )*136 + c];
                bf[j][1]=sBb[(ks*8+tig+4)*136 + c];
            }
#pragma unroll
            for (int i=0;i<4;i++)
#pragma unroll
                for (int j=0;j<4;j++) mma_f16(acc[i][j], af[i], bf[j]);
        }
    }
#undef ST_A
#undef ST_B

#pragma unroll
    for (int i=0;i<4;i++){
        int row = m0 + wm*64 + i*16 + gid;
        float bv0 = bias[row], bv8 = bias[row+8];
        float* y0 = Y + (size_t)(b*C_ + row)*T_;
        float* y8 = Y + (size_t)(b*C_ + row+8)*T_;
#pragma unroll
        for (int j=0;j<4;j++){
            int col = n0 + wn*32 + j*8 + tig*2;
            *(float2*)(y0+col)=make_float2(acc[i][j][0]+bv0, acc[i][j][1]+bv0);
            *(float2*)(y8+col)=make_float2(acc[i][j][2]+bv8, acc[i][j][3]+bv8);
        }
    }
}

/* =========== fp16 fused Q/K/V ============ */
__launch_bounds__(256,2)
__global__ void g_qkv(const __half* __restrict__ X2h,
                      const __half* __restrict__ Wq, const __half* __restrict__ Wk, const __half* __restrict__ Wv,
                      const float* __restrict__ bq, const float* __restrict__ bk, const float* __restrict__ bv,
                      __half* __restrict__ Yq, __half* __restrict__ Yk, __half* __restrict__ Yv)
{
    extern __shared__ char smraw[];
    __half* sA = (__half*)smraw;
    __half2* sB2 = (__half2*)(smraw + 4*4096*2);
    unsigned* sBu = (unsigned*)sB2;
    const int n0 = blockIdx.x*128;
    const int mi = blockIdx.y;
    const int sel = mi >> 2;
    const int m0 = (mi & 3)*128;
    const int b  = blockIdx.z;
    const __half* Wm = (sel==0)?Wq:(sel==1)?Wk:Wv;
    const float* bias= (sel==0)?bq:(sel==1)?bk:bv;
    const float alpha= (sel==0)?0.125f:1.f;

    const int tid = threadIdx.x;
    const int lane = tid & 31, wid = tid >> 5;
    const int gid = lane >> 2, tig = lane & 3;
    const int wm = wid & 1, wn = wid >> 1;

    const __half2* X2 = (const __half2*)X2h + (size_t)b*256*T_;
    const int rowB = tid >> 4, colB = (tid & 15)*8;

    float acc[4][4][4];
#pragma unroll
    for (int i=0;i<4;i++)
#pragma unroll
        for (int j=0;j<4;j++)
#pragma unroll
            for (int u=0;u<4;u++) acc[i][j][u]=0.f;

    const int KT = C_/32;
#define ST_A(st,K0) { const __half* ap = Wm + (size_t)(m0>>7)*65536 + (size_t)((K0)>>5)*4096 + tid*16; \
                      __half* d = sA + (st)*4096 + tid*16; cp16(d,ap); cp16(d+8,ap+8); }
#define ST_B(st,K0) { const __half2* bp = X2 + (size_t)(((K0)>>1) + rowB)*T_ + n0 + colB; \
                      __half2* d = sB2 + (st)*2176 + rowB*136 + colB; cp16(d,bp); cp16(d+4,bp+4); }
    ST_A(0,0)  ST_B(0,0)  CP_COMMIT;
    ST_A(1,32) ST_B(1,32) CP_COMMIT;
    ST_A(2,64) ST_B(2,64) CP_COMMIT;

    for (int kt=0; kt<KT; kt++){
        CP_WAIT2;
        __syncthreads();
        if (kt+3 < KT){ int st=(kt+3)&3; int K0=(kt+3)*32; ST_A(st,K0) ST_B(st,K0) }
        CP_COMMIT;
        const int buf = kt&3;
        __half* sAb = sA + buf*4096;
        unsigned* sBb = sBu + buf*2176;
#pragma unroll
        for (int ks=0;ks<2;ks++){
            unsigned af[4][4], bf[4][2];
            LOAD_AF16(af, sAb, wm, ks, lane)
#pragma unroll
            for (int j=0;j<4;j++){
                int c = wn*32 + j*8 + gid;
                bf[j][0]=sBb[(ks*8+tig  )*136 + c];
                bf[j][1]=sBb[(ks*8+tig+4)*136 + c];
            }
#pragma unroll
            for (int i=0;i<4;i++)
#pragma unroll
                for (int j=0;j<4;j++) mma_f16(acc[i][j], af[i], bf[j]);
        }
    }
#undef ST_A
#undef ST_B

#pragma unroll
    for (int i=0;i<4;i++){
        int row = m0 + wm*64 + i*16 + gid;
        float bv0 = bias[row], bv8 = bias[row+8];
        int h0 = row>>6, dv = row&63;
        if (sel==0){
            __half* base = Yq + (size_t)(b*H_+h0)*T_*64;
#pragma unroll
            for (int j=0;j<4;j++){
                int col = n0 + wn*32 + j*8 + tig*2;
                base[(size_t)col*64 + dv]        = __float2half_rn(alpha*(acc[i][j][0]+bv0));
                base[(size_t)(col+1)*64 + dv]    = __float2half_rn(alpha*(acc[i][j][1]+bv0));
                base[(size_t)col*64 + dv+8]      = __float2half_rn(alpha*(acc[i][j][2]+bv8));
                base[(size_t)(col+1)*64 + dv+8]  = __float2half_rn(alpha*(acc[i][j][3]+bv8));
            }
        } else if (sel==1){
            __half* base = Yk + (size_t)(b*H_+h0)*32*T_*2;
#pragma unroll
            for (int j=0;j<4;j++){
                int col = n0 + wn*32 + j*8 + tig*2;
                base[(((size_t)(dv>>1))*T_ + col)*2 + (dv&1)]       = __float2half_rn(acc[i][j][0]+bv0);
                base[(((size_t)(dv>>1))*T_ + col+1)*2 + (dv&1)]     = __float2half_rn(acc[i][j][1]+bv0);
                base[(((size_t)((dv+8)>>1))*T_ + col)*2 + (dv&1)]   = __float2half_rn(acc[i][j][2]+bv8);
                base[(((size_t)((dv+8)>>1))*T_ + col+1)*2 + (dv&1)] = __float2half_rn(acc[i][j][3]+bv8);
            }
        } else {
            __half* base = Yv + (size_t)(b*H_+h0)*256*64*2;
#pragma unroll
            for (int j=0;j<4;j++){
                int col = n0 + wn*32 + j*8 + tig*2;
                base[(((size_t)(col>>1))*64 + dv)*2 + 0]   = __float2half_rn(acc[i][j][0]+bv0);
                base[(((size_t)(col>>1))*64 + dv)*2 + 1]   = __float2half_rn(acc[i][j][1]+bv0);
                base[(((size_t)(col>>1))*64 + dv+8)*2 + 0] = __float2half_rn(acc[i][j][2]+bv8);
                base[(((size_t)(col>>1))*64 + dv+8)*2 + 1] = __float2half_rn(acc[i][j][3]+bv8);
            }
        }
    }
}

/* =========== fp16 scores: P = Qh @ Kh, out fp32 ============ */
__launch_bounds__(256,2)
__global__ void g_sc(const __half* __restrict__ Qh, const __half* __restrict__ Kh,
                     float* __restrict__ P)
{
    extern __shared__ char smraw[];
    __half* sA = (__half*)smraw;
    unsigned* sBu = (unsigned*)(smraw + 4*5120*2);
    const int s0 = blockIdx.x*128;
    const int t0 = blockIdx.y*128;
    const int bh = blockIdx.z;
    const int tid = threadIdx.x;
    const int lane = tid & 31, wid = tid >> 5;
    const int gid = lane >> 2, tig = lane & 3;
    const int wm = wid & 1, wn = wid >> 1;

    const __half* qb = Qh + (size_t)bh*T_*64;
    const __half2* kb = (const __half2*)Kh + (size_t)bh*32*T_;
    const int rowA = tid >> 1, colA = (tid & 1)*16;
    const int rowB = tid >> 4, colB = (tid & 15)*8;

    float acc[4][4][4];
#pragma unroll
    for (int i=0;i<4;i++)
#pragma unroll
        for (int j=0;j<4;j++)
#pragma unroll
            for (int u=0;u<4;u++) acc[i][j][u]=0.f;

#define ST_A(st,K0) { const __half* ap = qb + (size_t)(t0+rowA)*64 + (K0) + colA; \
                      __half* d = sA + (st)*5120 + rowA*40 + colA; cp16(d,ap); cp16(d+8,ap+8); }
#define ST_B(st,K0) { const __half2* bp = kb + (size_t)(((K0)>>1)+rowB)*T_ + s0 + colB; \
                      __half2* d = (__half2*)sBu + (size_t)(st)*2176 + rowB*136 + colB; \
                      cp16(d,bp); cp16(d+4,bp+4); }
    ST_A(0,0)  ST_B(0,0)  CP_COMMIT;
    ST_A(1,32) ST_B(1,32) CP_COMMIT;
    CP_COMMIT;

    for (int kt=0; kt<2; kt++){
        CP_WAIT2;
        __syncthreads();
        CP_COMMIT;
        const int buf = kt;
        __half* sAb = sA + buf*5120;
        unsigned* sBb = sBu + buf*2176;
#pragma unroll
        for (int ks=0;ks<2;ks++){
            unsigned af[4][4], bf[4][2];
#pragma unroll
            for (int i=0;i<4;i++){
                int r = wm*64 + i*16 + gid;
                af[i][0]=*(const unsigned*)(sAb + (size_t)r*40 + ks*16 + tig*2);
                af[i][1]=*(const unsigned*)(sAb + (size_t)(r+8)*40 + ks*16 + tig*2);
                af[i][2]=*(const unsigned*)(sAb + (size_t)r*40 + ks*16 + tig*2 + 8);
                af[i][3]=*(const unsigned*)(sAb + (size_t)(r+8)*40 + ks*16 + tig*2 + 8);
            }
#pragma unroll
            for (int j=0;j<4;j++){
                int c = wn*32 + j*8 + gid;
                bf[j][0]=sBb[(ks*8+tig  )*136 + c];
                bf[j][1]=sBb[(ks*8+tig+4)*136 + c];
            }
#pragma unroll
            for (int i=0;i<4;i++)
#pragma unroll
                for (int j=0;j<4;j++) mma_f16(acc[i][j], af[i], bf[j]);
        }
    }
#undef ST_A
#undef ST_B

#pragma unroll
    for (int i=0;i<4;i++){
        int row = t0 + wm*64 + i*16 + gid;
        float* y0 = P + ((size_t)bh*T_ + row)*T_;
        float* y8 = P + ((size_t)bh*T_ + row+8)*T_;
#pragma unroll
        for (int j=0;j<4;j++){
            int col = s0 + wn*32 + j*8 + tig*2;
            *(float2*)(y0+col)=make_float2(acc[i][j][0], acc[i][j][1]);
            *(float2*)(y8+col)=make_float2(acc[i][j][2], acc[i][j][3]);
        }
    }
}

/* =========== fp16 ctx: Ph @ Vh + rel-V band -> hC packed fp16 ============ */
__launch_bounds__(256,2)
__global__ void g_ctx(const __half* __restrict__ Ph, const __half* __restrict__ Vh,
                      const float* __restrict__ erv, __half* __restrict__ Ch)
{
    extern __shared__ char smraw[];
    __half* sA = (__half*)smraw;
    unsigned* sBu = (unsigned*)(smraw + 4*5120*2);
    float* sErv = (float*)(smraw + 4*5120*2 + 4*1152*4);
    const int t0 = blockIdx.x*128;
    const int bh = blockIdx.y;
    const int b  = bh >> 3, h = bh & 7;
    const int tid = threadIdx.x;
    const int lane = tid & 31, wid = tid >> 5;
    const int gid = lane >> 2, tig = lane & 3;
    const int wm = wid & 1, wn = wid >> 1;

    const __half* pb = Ph + (size_t)bh*T_*T_;
    const __half2* vb = (const __half2*)Vh + (size_t)bh*256*64;
    const int rowA = tid >> 1, colA = (tid & 1)*16;
    const int rowB = tid >> 4, colB = (tid & 15)*4;

    for (int l=tid; l<21*64; l+=256) sErv[l]=erv[l];

    float acc[4][2][4];
#pragma unroll
    for (int i=0;i<4;i++)
#pragma unroll
        for (int j=0;j<2;j++)
#pragma unroll
            for (int u=0;u<4;u++) acc[i][j][u]=0.f;

#define ST_A(st,K0) { const __half* ap = pb + (size_t)(t0+rowA)*T_ + (K0) + colA; \
                      __half* d = sA + (st)*5120 + rowA*40 + colA; cp16(d,ap); cp16(d+8,ap+8); }
#define ST_B(st,K0) { const __half2* bp = vb + (size_t)(((K0)>>1)+rowB)*64 + colB; \
                      __half2* d = (__half2*)sBu + (size_t)(st)*1152 + rowB*72 + colB; cp16(d,bp); }
    ST_A(0,0)  ST_B(0,0)  CP_COMMIT;
    ST_A(1,32) ST_B(1,32) CP_COMMIT;
    ST_A(2,64) ST_B(2,64) CP_COMMIT;

    const int KT = T_/32;
    for (int kt=0; kt<KT; kt++){
        CP_WAIT2;
        __syncthreads();
        if (kt+3 < KT){ int st=(kt+3)&3; int K0=(kt+3)*32; ST_A(st,K0) ST_B(st,K0) }
        CP_COMMIT;
        const int buf = kt&3;
        __half* sAb = sA + buf*5120;
        unsigned* sBb = sBu + buf*1152;
#pragma unroll
        for (int ks=0;ks<2;ks++){
            unsigned af[4][4], bf[2][2];
#pragma unroll
            for (int i=0;i<4;i++){
                int r = wm*64 + i*16 + gid;
                af[i][0]=*(const unsigned*)(sAb + (size_t)r*40 + ks*16 + tig*2);
                af[i][1]=*(const unsigned*)(sAb + (size_t)(r+8)*40 + ks*16 + tig*2);
                af[i][2]=*(const unsigned*)(sAb + (size_t)r*40 + ks*16 + tig*2 + 8);
                af[i][3]=*(const unsigned*)(sAb + (size_t)(r+8)*40 + ks*16 + tig*2 + 8);
            }
#pragma unroll
            for (int j=0;j<2;j++){
                int c = wn*16 + j*8 + gid;
                bf[j][0]=sBb[(ks*8+tig  )*72 + c];
                bf[j][1]=sBb[(ks*8+tig+4)*72 + c];
            }
#pragma unroll
            for (int i=0;i<4;i++)
#pragma unroll
                for (int j=0;j<2;j++) mma_f16(acc[i][j], af[i], bf[j]);
        }
    }
#undef ST_A
#undef ST_B

#pragma unroll
    for (int i=0;i<4;i++){
#pragma unroll
        for (int rr=0; rr<2; rr++){
            int t = t0 + wm*64 + i*16 + gid + rr*8;
            const __half* prow = pb + (size_t)t*T_;
            for (int r=0;r<21;r++){
                int s = t + r - WIN_;
                if ((unsigned)s < (unsigned)T_){
                    float pv = __half2float(prow[s]);
#pragma unroll
                    for (int j=0;j<2;j++){
                        int d = wn*16 + j*8 + tig*2;
                        acc[i][j][rr*2+0] += pv*sErv[r*64 + d];
                        acc[i][j][rr*2+1] += pv*sErv[r*64 + d+1];
                    }
                }
            }
        }
    }

    __half2* C2 = (__half2*)Ch;
#pragma unroll
    for (int i=0;i<4;i++){
        int row = t0 + wm*64 + i*16 + gid;
#pragma unroll
        for (int j=0;j<2;j++){
            int c = h*64 + wn*16 + j*8 + tig*2;
            __half2* cp = C2 + (size_t)(b*256 + (c>>1))*T_;
            cp[row]   = __floats2half2_rn(acc[i][j][0], acc[i][j][1]);
            cp[row+8] = __floats2half2_rn(acc[i][j][2], acc[i][j][3]);
        }
    }
}

/* =========== fp16 K=3 conv as 3 tap-GEMMs =========== */
__launch_bounds__(256,2)
__global__ void gconv3p(const __half* __restrict__ Xp, const __half* __restrict__ Wc,
                        const float* __restrict__ bias, const float* __restrict__ mask,
                        float* __restrict__ Y, __half* __restrict__ Yh,
                        int Cin, int Cout, int mode, int ktiles)
{
    extern __shared__ char smraw[];
    __half* sA = (__half*)smraw;
    __half* sX = (__half*)(smraw + 4*6144*2);
    const int n0 = blockIdx.x*128;
    const int m0 = blockIdx.y*128;
    const int bz = blockIdx.z;
    const int b    = (mode==1) ? (bz & 7) : bz;
    const int part = (mode==1) ? (bz >> 3) : 0;
    const int kOff16 = part*ktiles;

    const int tid = threadIdx.x;
    const int lane = tid & 31, wid = tid >> 5;
    const int gid = lane >> 2, tig = lane & 3;
    const int wm = wid & 1, wn = wid >> 1;

    const __half* xb = Xp + (size_t)b*516*Cin;
    const size_t wmt = (size_t)(m0>>7)*((size_t)Cin*384);

    float acc[4][4][4];
#pragma unroll
    for (int i=0;i<4;i++)
#pragma unroll
        for (int j=0;j<4;j++)
#pragma unroll
            for (int u=0;u<4;u++) acc[i][j][u]=0.f;

#define ST_A(st,ct) { const __half* ap = Wc + wmt + (size_t)(ct)*6144 + tid*24; \
                      __half* d = sA + (st)*6144 + tid*24; \
                      cp16(d,ap); cp16(d+8,ap+8); cp16(d+16,ap+16); }
#define ST_B(st,ct) { int c0 = (ct)*16; \
                      { int r = tid>>1, q = tid&1; \
                        const __half* bp = xb + (size_t)(n0 + r)*Cin + c0 + q*8; \
                        cp16(sX + (st)*3120 + r*24 + q*8, bp); } \
                      { int slot = tid+256; if (slot < 260){ int r = slot>>1, q = slot&1; \
                        const __half* bp = xb + (size_t)(n0 + r)*Cin + c0 + q*8; \
                        cp16(sX + (st)*3120 + r*24 + q*8, bp); } } }
    if (0 < ktiles){ ST_A(0,kOff16)   ST_B(0,kOff16)   } CP_COMMIT;
    if (1 < ktiles){ ST_A(1,kOff16+1) ST_B(1,kOff16+1) } CP_COMMIT;
    if (2 < ktiles){ ST_A(2,kOff16+2) ST_B(2,kOff16+2) } CP_COMMIT;

    for (int kt=0; kt<ktiles; kt++){
        CP_WAIT2;
        __syncthreads();
        if (kt+3 < ktiles){ int st=(kt+3)&3; int ct=kOff16+kt+3; ST_A(st,ct) ST_B(st,ct) }
        CP_COMMIT;
        const int buf = kt&3;
        const __half* sAb = sA + buf*6144;
        const unsigned* sXu = (const unsigned*)(sX + buf*3120);
#pragma unroll
        for (int tap=0; tap<3; tap++){
            unsigned af[4][4], bf[4][2];
#pragma unroll
            for (int i=0;i<4;i++){
                const float4 av = *(const float4*)(sAb + tap*2048 + ((wm*4+i)*32 + lane)*8);
                af[i][0]=__float_as_uint(av.x); af[i][1]=__float_as_uint(av.y);
                af[i][2]=__float_as_uint(av.z); af[i][3]=__float_as_uint(av.w);
            }
#pragma unroll
            for (int j=0;j<4;j++){
                int rrow = wn*32 + j*8 + gid + tap;
                bf[j][0]=sXu[rrow*12 + tig    ];
                bf[j][1]=sXu[rrow*12 + tig + 4];
            }
#pragma unroll
            for (int i=0;i<4;i++)
#pragma unroll
                for (int j=0;j<4;j++) mma_f16(acc[i][j], af[i], bf[j]);
        }
    }
#undef ST_A
#undef ST_B

    if (mode==0){
        const float* mb = mask + b*T_;
#pragma unroll
        for (int i=0;i<4;i++){
            int row = m0 + wm*64 + i*16 + gid;
            float bv0 = bias[row], bv8 = bias[row+8];
#pragma unroll
            for (int j=0;j<4;j++){
                int col = n0 + wn*32 + j*8 + tig*2;
                float m0v = mb[col], m1v = mb[col+1];
                __half* p0 = Yh + (size_t)(b*516 + col+1)*F_;
                __half* p1 = Yh + (size_t)(b*516 + col+2)*F_;
                p0[row]   = __float2half_rn(fmaxf(acc[i][j][0]+bv0, 0.f)*m0v);
                p1[row]   = __float2half_rn(fmaxf(acc[i][j][1]+bv0, 0.f)*m1v);
                p0[row+8] = __float2half_rn(fmaxf(acc[i][j][2]+bv8, 0.f)*m0v);
                p1[row+8] = __float2half_rn(fmaxf(acc[i][j][3]+bv8, 0.f)*m1v);
            }
        }
    } else {
#pragma unroll
        for (int i=0;i<4;i++){
            int row = m0 + wm*64 + i*16 + gid;
            float* y0 = Y + (size_t)part*ELT_X + (size_t)(b*Cout + row)*T_;
            float* y8 = Y + (size_t)part*ELT_X + (size_t)(b*Cout + row+8)*T_;
#pragma unroll
            for (int j=0;j<4;j++){
                int col = n0 + wn*32 + j*8 + tig*2;
                *(float2*)(y0+col)=make_float2(acc[i][j][0], acc[i][j][1]);
                *(float2*)(y8+col)=make_float2(acc[i][j][2], acc[i][j][3]);
            }
        }
    }
}

/* ---- banded relative-K logits (fp16 Q) ---- */
__global__ void k_relband(const __half* __restrict__ Qh, const float* __restrict__ erk,
                          float* __restrict__ P)
{
    const int bh = blockIdx.y;
    const int t = blockIdx.x*8 + (threadIdx.x>>5);
    const int lane = threadIdx.x & 31;
    const __half* qr = Qh + ((size_t)bh*T_ + t)*64;
    float q0 = __half2float(qr[lane]);
    float q1 = __half2float(qr[32+lane]);
    float* prow = P + ((size_t)bh*T_ + t)*T_;
    for (int r=0;r<21;r++){
        float pd = q0*erk[r*64+lane] + q1*erk[r*64+32+lane];
#pragma unroll
        for (int o=16;o;o>>=1) pd += __shfl_xor_sync(0xffffffffu, pd, o);
        int s = t + r - WIN_;
        if (lane==0 && (unsigned)s < (unsigned)T_) prow[s] += pd;
    }
}

/* ---- row softmax: reads fp32 P, writes fp16 Ph ---- */
__launch_bounds__(256)
__global__ void k_softmax(const float* __restrict__ P, const float* __restrict__ mask,
                          __half* __restrict__ Ph)
{
    const int row = blockIdx.x;
    const int t  = row & (T_-1);
    const int bh = row >> 9;
    const int b  = bh >> 3;
    const float* p = P + (size_t)row*T_;
    __half* ph = Ph + (size_t)row*T_;
    const float* mb = mask + b*T_;
    const int tid = threadIdx.x;
    const int lane = tid & 31, w = tid >> 5;
    const float mt = mb[t];
    float v0 = (mt*mb[tid]     != 0.f) ? p[tid]     : -1e4f;
    float v1 = (mt*mb[tid+256] != 0.f) ? p[tid+256] : -1e4f;
    __shared__ float red[8];
    float m = fmaxf(v0,v1);
#pragma unroll
    for (int o=16;o;o>>=1) m = fmaxf(m, __shfl_xor_sync(0xffffffffu, m, o));
    if (lane==0) red[w]=m;
    __syncthreads();
    float mx = red[0];
#pragma unroll
    for (int k2=1;k2<8;k2++) mx = fmaxf(mx, red[k2]);
    float e0 = expf(v0-mx), e1 = expf(v1-mx);
    float s = e0+e1;
#pragma unroll
    for (int o=16;o;o>>=1) s += __shfl_xor_sync(0xffffffffu, s, o);
    __syncthreads();
    if (lane==0) red[w]=s;
    __syncthreads();
    float tot = 0.f;
#pragma unroll
    for (int k2=0;k2<8;k2++) tot += red[k2];
    float inv = 1.f/tot;
    ph[tid]     = __float2half_rn(e0*inv);
    ph[tid+256] = __float2half_rn(e1*inv);
}

/* ---- residual add + LN (after attention); emits padded fp16 x ---- */
__launch_bounds__(512)
__global__ void k_addln(float* __restrict__ X, const float* __restrict__ Yv,
                        const float* __restrict__ gamma, const float* __restrict__ beta,
                        __half* __restrict__ Xp, const float* __restrict__ mask)
{
    const int b = blockIdx.y;
    const int tl = threadIdx.x & 31;
    const int slot = threadIdx.x >> 5;
    const int t = blockIdx.x*32 + tl;
    __shared__ float ssum[16][33];
    __shared__ float ssq[16][33];
    float vals[32];
    float s=0.f, q=0.f;
    size_t base = (size_t)b*C_*T_ + t;
#pragma unroll
    for (int u=0;u<32;u++){
        int c = slot*32+u;
        float v = X[base + (size_t)c*T_] + Yv[base + (size_t)c*T_];
        vals[u]=v; s+=v; q+=v*v;
    }
    ssum[slot][tl]=s; ssq[slot][tl]=q;
    __syncthreads();
    float m=0.f, vv=0.f;
#pragma unroll
    for (int k2=0;k2<16;k2++){ m+=ssum[k2][tl]; vv+=ssq[k2][tl]; }
    m *= (1.f/512.f);
    vv = vv*(1.f/512.f) - m*m;
    float r = rsqrtf(vv + 1e-5f);
    float mk = mask[b*T_ + t];
#pragma unroll
    for (int u=0;u<32;u++){
        int c = slot*32+u;
        float o = (vals[u]-m)*r*gamma[c] + beta[c];
        X[base + (size_t)c*T_] = o;
        Xp[(size_t)(b*516 + t+1)*C_ + c] = __float2half_rn(o*mk);
    }
}

/* ---- fused: conv split-K reduce + bias + mask + residual + LN;
       emits packed-pair fp16; optionally writes final masked output ---- */
__launch_bounds__(512)
__global__ void k_addln2(float* __restrict__ X, const float* __restrict__ P0,
                         const float* __restrict__ bias2,
                         const float* __restrict__ gamma, const float* __restrict__ beta,
                         __half* __restrict__ Xr, const float* __restrict__ mask,
                         float* __restrict__ Out)
{
    const int b = blockIdx.y;
    const int tl = threadIdx.x & 31;
    const int slot = threadIdx.x >> 5;
    const int t = blockIdx.x*32 + tl;
    __shared__ float ssum[16][33];
    __shared__ float ssq[16][33];
    float vals[32];
    float s=0.f, q=0.f;
    size_t base = (size_t)b*C_*T_ + t;
    const float mk = mask[b*T_ + t];
#pragma unroll
    for (int u=0;u<32;u++){
        int c = slot*32+u;
        size_t idx = base + (size_t)c*T_;
        float y = (P0[idx] + P0[(size_t)ELT_X + idx] + bias2[c]) * mk;
        float v = X[idx] + y;
        vals[u]=v; s+=v; q+=v*v;
    }
    ssum[slot][tl]=s; ssq[slot][tl]=q;
    __syncthreads();
    float m=0.f, vv=0.f;
#pragma unroll
    for (int k2=0;k2<16;k2++){ m+=ssum[k2][tl]; vv+=ssq[k2][tl]; }
    m *= (1.f/512.f);
    vv = vv*(1.f/512.f) - m*m;
    float r = rsqrtf(vv + 1e-5f);
#pragma unroll
    for (int u=0;u<32;u++){
        int c = slot*32+u;
        float o = (vals[u]-m)*r*gamma[c] + beta[c];
        X[base + (size_t)c*T_] = o;
        Xr[((size_t)(b*256 + (c>>1))*T_ + t)*2 + (c&1)] = __float2half_rn(o);
        if (Out) Out[base + (size_t)c*T_] = o*mk;
    }
}

/* ---------------- host orchestration ---------------- */
extern "C" void kernel_launch(void* const* d_in, const int* in_sizes, int n_in,
                              void* d_out, int out_size)
{
    (void)in_sizes; (void)n_in; (void)out_size;
    const float* x_in = (const float*)d_in[0];
    const float* mask = (const float*)d_in[1];
    const float* Wq  = (const float*)d_in[2];
    const float* bq  = (const float*)d_in[3];
    const float* Wk  = (const float*)d_in[4];
    const float* bk  = (const float*)d_in[5];
    const float* Wv  = (const float*)d_in[6];
    const float* bv  = (const float*)d_in[7];
    const float* Wo  = (const float*)d_in[8];
    const float* bo  = (const float*)d_in[9];
    const float* erk = (const float*)d_in[10];
    const float* erv = (const float*)d_in[11];
    const float* g1  = (const float*)d_in[12];
    const float* b1  = (const float*)d_in[13];
    const float* g2  = (const float*)d_in[14];
    const float* b2  = (const float*)d_in[15];
    const float* W1  = (const float*)d_in[16];
    const float* bf1 = (const float*)d_in[17];
    const float* W2  = (const float*)d_in[18];
    const float* bf2 = (const float*)d_in[19];

    const int SM_GW  = 4*(4096 + 2176*2)*2;
    const int SM_SC  = 4*5120*2 + 4*2176*4;
    const int SM_CTX = 4*5120*2 + 4*1152*4 + 21*64*4;
    const int SM_CV  = 4*(6144 + 3120)*2;
    cudaFuncSetAttribute(g1x1,   cudaFuncAttributeMaxDynamicSharedMemorySize, SM_GW);
    cudaFuncSetAttribute(g_qkv,  cudaFuncAttributeMaxDynamicSharedMemorySize, SM_GW);
    cudaFuncSetAttribute(g_sc,   cudaFuncAttributeMaxDynamicSharedMemorySize, SM_SC);
    cudaFuncSetAttribute(g_ctx,  cudaFuncAttributeMaxDynamicSharedMemorySize, SM_CTX);
    cudaFuncSetAttribute(gconv3p,cudaFuncAttributeMaxDynamicSharedMemorySize, SM_CV);

    float* pool = 0;
    cudaGetSymbolAddress((void**)&pool, g_pool);
    float* px = pool;
    float* pq = pool + (size_t)1*ELT_X;   /* conv split-K partials (slots 1,2) */
    float* py = pool + (size_t)3*ELT_X;   /* Wo output */
    float* pp = pool + (size_t)4*ELT_X;   /* scores fp32 (ELT_P) */
    __half* hb  = (__half*)(pool + (size_t)4*ELT_X + ELT_P + ELT_X);
    __half* hXr  = hb;
    __half* hC   = hXr + (size_t)ELT_X;
    __half* hXp1 = hC  + (size_t)ELT_X;
    __half* hXp2 = hXp1 + (size_t)B_*516*C_;
    __half* hWq  = hXp2 + (size_t)B_*516*F_;
    __half* hWk  = hWq + WQKV;
    __half* hWv  = hWk + WQKV;
    __half* hWo  = hWv + WQKV;
    __half* hW1  = hWo + WQKV;
    __half* hW2  = hW1 + WFF;
    __half* hQ   = hW2 + WFF;
    __half* hK   = hQ + (size_t)ELT_X;
    __half* hV   = hK + (size_t)ELT_X;
    __half* hP   = hV + (size_t)ELT_X;

    /* combined weight swizzle: total 8-groups = 4*WQKV/8 + 2*WFF/8 = 5,505,024 */
    k_swizAll<<<21504,256>>>(Wq, Wk, Wv, Wo, W1, W2, hWq, hWk, hWv, hWo, hW1, hW2);

    k_maskmul2<<<ELT_X/256,256>>>(x_in, mask, px, hXr);
    k_zb16<<<20480/256,256>>>(hXp1, hXp2);

    size_t mszQ = (size_t)C_*C_;
    for (int L=0;L<6;L++){
        g_qkv<<<dim3(T_/128, 12, B_),256,SM_GW>>>(hXr, hWq + L*mszQ, hWk + L*mszQ, hWv + L*mszQ,
                                                  bq+L*C_, bk+L*C_, bv+L*C_, hQ, hK, hV);
        g_sc<<<dim3(T_/128, T_/128, B_*H_),256,SM_SC>>>(hQ, hK, pp);
        k_relband<<<dim3(T_/8, B_*H_),256>>>(hQ, erk + L*21*64, pp);
        k_softmax<<<B_*H_*T_,256>>>(pp, mask, hP);
        g_ctx<<<dim3(T_/128, B_*H_),256,SM_CTX>>>(hP, hV, erv + L*21*64, hC);
        g1x1<<<dim3(T_/128, C_/128, B_),256,SM_GW>>>(hWo + L*mszQ, hC, bo + L*C_, py);
        k_addln<<<dim3(T_/32,B_),512>>>(px, py, g1+L*C_, b1+L*C_, hXp1, mask);

        gconv3p<<<dim3(T_/128, F_/128, B_),256,SM_CV>>>(hXp1, hW1 + (size_t)L*F_*C_*3,
                                                        bf1+L*F_, mask, (float*)0, hXp2,
                                                        C_, F_, 0, C_/16);
        gconv3p<<<dim3(T_/128, C_/128, 2*B_),256,SM_CV>>>(hXp2, hW2 + (size_t)L*C_*F_*3,
                                                          bf2+L*C_, mask, pq, (__half*)0,
                                                          F_, C_, 1, F_/32);
        k_addln2<<<dim3(T_/32,B_),512>>>(px, pq, bf2+L*C_, g2+L*C_, b2+L*C_, hXr, mask,
                                         (L==5) ? (float*)d_out : (float*)0);
    }
}